// round 11
// baseline (speedup 1.0000x reference)
#include <cuda_runtime.h>
#include <cuda_bf16.h>
#include <cstdint>
#include <math.h>

#define D 256
#define LDS 72   // smem row stride in bf16 (64 data + 8 pad)

// ===========================================================================
// Static device scratch (unified global row space per level: tern rows first)
// ===========================================================================
__device__ float g_nodes[65536 * D];
__device__ __nv_bfloat16 g_Xt_img[4096  * 1536];        // ternary X [hi768|lo768]
__device__ __nv_bfloat16 g_Xb_img[12288 * 1024];        // binary  X [hi512|lo512]
__device__ __nv_bfloat16 g_H_img [16384 * 1024];        // H [hi512|lo512], global rows
__device__ float g_R[16384 * D];
__device__ int   g_nodes_l[16384];
__device__ int   g_op_l[16384];
__device__ __nv_bfloat16 g_W1b_img[512 * 1024];
__device__ __nv_bfloat16 g_W1t_img[512 * 1536];
__device__ __nv_bfloat16 g_W2b_img[256 * 1024];
__device__ __nv_bfloat16 g_W2t_img[256 * 1024];
__device__ float g_opb_b[16 * 512];
__device__ float g_opb_t[16 * 512];

// ===========================================================================
// Helpers (sm_80-era PTX only)
// ===========================================================================
__device__ __forceinline__ uint32_t smem_u32(const void* p) {
    uint32_t a;
    asm("{ .reg .u64 t; cvta.to.shared.u64 t, %1; cvt.u32.u64 %0, t; }" : "=r"(a) : "l"(p));
    return a;
}
__device__ __forceinline__ void cp_async16(uint32_t saddr, const void* gaddr) {
    asm volatile("cp.async.cg.shared.global [%0], [%1], 16;" :: "r"(saddr), "l"(gaddr));
}
__device__ __forceinline__ void cp_commit() {
    asm volatile("cp.async.commit_group;");
}
__device__ __forceinline__ void ldsm_x4(uint32_t* r, uint32_t addr) {
    asm volatile("ldmatrix.sync.aligned.m8n8.x4.shared.b16 {%0,%1,%2,%3}, [%4];"
                 : "=r"(r[0]), "=r"(r[1]), "=r"(r[2]), "=r"(r[3]) : "r"(addr));
}
__device__ __forceinline__ void mma_bf16(float* c, const uint32_t* a, uint32_t b0, uint32_t b1) {
    asm volatile("mma.sync.aligned.m16n8k16.row.col.f32.bf16.bf16.f32 "
                 "{%0,%1,%2,%3}, {%4,%5,%6,%7}, {%8,%9}, {%0,%1,%2,%3};"
                 : "+f"(c[0]), "+f"(c[1]), "+f"(c[2]), "+f"(c[3])
                 : "r"(a[0]), "r"(a[1]), "r"(a[2]), "r"(a[3]), "r"(b0), "r"(b1));
}
__device__ __forceinline__ float gelu_exact(float a) {
    return 0.5f * a * (1.0f + erff(a * 0.70710678118654752f));
}

// ===========================================================================
// Combined setup: weight images ([hi(K)|lo(K)] per output row) + op tables
// ===========================================================================
__device__ __forceinline__ void wprep_body(const float* __restrict__ W,
                                           __nv_bfloat16* __restrict__ img,
                                           int K, int N, int idx) {
    if (idx >= K * N) return;
    int k = idx / N, n = idx % N;
    float v = W[idx];
    __nv_bfloat16 hi = __float2bfloat16(v);
    __nv_bfloat16 lo = __float2bfloat16(v - __bfloat162float(hi));
    size_t base = (size_t)n * 2 * K;
    img[base + k] = hi;
    img[base + K + k] = lo;
}
__device__ __forceinline__ void opproj_body(const float* __restrict__ op_table,
                                            const float* __restrict__ W1,
                                            const float* __restrict__ b1,
                                            float* __restrict__ outb, int idx) {
    int o = idx >> 9, j = idx & 511;
    float s = b1[j];
    const float* oe = op_table + o * D;
    #pragma unroll 8
    for (int k = 0; k < D; k++)
        s = fmaf(oe[k], W1[(size_t)k * 512 + j], s);
    outb[idx] = s;
}
__global__ void setup_kernel(const float* __restrict__ W1b, const float* __restrict__ b1b,
                             const float* __restrict__ W2b,
                             const float* __restrict__ W1t, const float* __restrict__ b1t,
                             const float* __restrict__ W2t,
                             const float* __restrict__ op_table) {
    int b = blockIdx.x, tid = threadIdx.x;
    if (b < 1024)      wprep_body(W1b + 256 * 512, g_W1b_img, 512, 512, b * 256 + tid);
    else if (b < 2560) wprep_body(W1t + 256 * 512, g_W1t_img, 768, 512, (b - 1024) * 256 + tid);
    else if (b < 3072) wprep_body(W2b, g_W2b_img, 512, 256, (b - 2560) * 256 + tid);
    else if (b < 3584) wprep_body(W2t, g_W2t_img, 512, 256, (b - 3072) * 256 + tid);
    else if (b < 3616) opproj_body(op_table, W1b, b1b, g_opb_b, (b - 3584) * 256 + tid);
    else               opproj_body(op_table, W1t, b1t, g_opb_t, (b - 3616) * 256 + tid);
}

// ===========================================================================
// X prep (merged tern/bin): gg < tern_cnt -> ternary row gg of Xt;
// else binary row (gg - tern_cnt) of Xb. Global row = gg.
// ===========================================================================
template <bool LEAF>
__global__ void prep_kernel(const int* __restrict__ lvl_idx, int phases, int tern_cnt,
                            const int* __restrict__ op_ids,
                            const int* __restrict__ lc, const int* __restrict__ rc,
                            const int* __restrict__ tc,
                            const int* __restrict__ comp_ids,
                            const float* __restrict__ comp_table) {
    int gg = blockIdx.x;
    bool tern = gg < tern_cnt;
    __shared__ int sids[3];
    int d = threadIdx.x;
    if (d == 0) {
        int pos = (gg & 4095) * phases + (gg >> 12);
        int node = lvl_idx[pos];
        int l = lc[node], r = rc[node];
        sids[0] = LEAF ? comp_ids[l] : l;
        sids[1] = LEAF ? comp_ids[r] : r;
        if (tern) { int t = tc[node]; sids[2] = LEAF ? comp_ids[t] : t; }
        g_nodes_l[gg] = node;
        g_op_l[gg] = op_ids[node];
    }
    __syncthreads();
    const float* src = LEAF ? comp_table : g_nodes;
    float lev = src[(size_t)sids[0] * D + d];
    float rev = src[(size_t)sids[1] * D + d];
    if (tern) {
        float tev = src[(size_t)sids[2] * D + d];
        __nv_bfloat16* row = g_Xt_img + (size_t)gg * 1536;
        float xs[3] = {lev, rev, tev};
        #pragma unroll
        for (int s = 0; s < 3; s++) {
            __nv_bfloat16 hi = __float2bfloat16(xs[s]);
            __nv_bfloat16 lo = __float2bfloat16(xs[s] - __bfloat162float(hi));
            row[s * D + d] = hi;
            row[768 + s * D + d] = lo;
        }
        g_R[(size_t)gg * D + d] = (lev + rev + tev) * (1.0f / 3.0f);
    } else {
        __nv_bfloat16* row = g_Xb_img + (size_t)(gg - tern_cnt) * 1024;
        float xs[2] = {lev, rev};
        #pragma unroll
        for (int s = 0; s < 2; s++) {
            __nv_bfloat16 hi = __float2bfloat16(xs[s]);
            __nv_bfloat16 lo = __float2bfloat16(xs[s] - __bfloat162float(hi));
            row[s * D + d] = hi;
            row[512 + s * D + d] = lo;
        }
        g_R[(size_t)gg * D + d] = lev + rev;
    }
}

// ===========================================================================
// HMMA GEMM, 512 threads, split-K x2 (kg0 even chunks / kg1 odd, 4-buf ring).
// Logical K = [hi|lo|hi] x [whi|whi|wlo] over 2-term physical images:
//   srcA = c<2KC ? c : c-2KC ; srcB = c<KC ? c : c-KC.
// MODE 0: 128x128, segment by blockIdx.x<nblk0 (tern/bin), opbias+gelu -> H.
// MODE 1: 64x256, segment by row, bias+residual+LN -> scatter g_nodes.
// MODE 2: like 1 but dense out[row].
// ===========================================================================
template <int MODE>
__global__ void __launch_bounds__(512, 1)
mma_kernel(const __nv_bfloat16* __restrict__ A0, const __nv_bfloat16* __restrict__ B0,
           const float* __restrict__ bias0, int KC0, int nblk0,
           const __nv_bfloat16* __restrict__ A1, const __nv_bfloat16* __restrict__ B1,
           const float* __restrict__ bias1, int KC1,
           __nv_bfloat16* __restrict__ Himg, const float* __restrict__ Rres,
           const float* __restrict__ gamma, const float* __restrict__ beta,
           float* __restrict__ outp) {
    constexpr int TM = (MODE == 0) ? 128 : 64;
    constexpr int TN = (MODE == 0) ? 128 : 256;
    constexpr int CHUNKE = (TM + TN) * LDS;     // bf16 elems per buffer
    constexpr int WM = TM / 32;

    extern __shared__ char smem[];
    const uint32_t sbase = smem_u32(smem);
    const int tid = threadIdx.x, wid = tid >> 5, lane = tid & 31;
    const int kg = wid >> 3, wl = wid & 7;
    const int warp_m = wl & (WM - 1), warp_n = wl / WM;
    const int wm0 = warp_m * 32, wn0 = warp_n * 64;
    const int bx = blockIdx.x;
    const int cb0 = (MODE == 0) ? blockIdx.y * 128 : 0;

    int KC, grow0, arow0;
    const __nv_bfloat16 *Aimg, *Bimg;
    const float* bvec;
    if (MODE == 0) {
        if (bx < nblk0) { KC = KC0; Aimg = A0; Bimg = B0; bvec = bias0; arow0 = bx * 128; grow0 = arow0; }
        else { KC = KC1; Aimg = A1; Bimg = B1; bvec = bias1;
               arow0 = (bx - nblk0) * 128; grow0 = nblk0 * 128 + arow0; }
    } else {
        grow0 = bx * 64; arow0 = grow0; Aimg = A0;
        if (bx < nblk0) { KC = KC0; Bimg = B0; bvec = bias0; }
        else            { KC = KC1; Bimg = B1; bvec = bias1; }
    }
    const int stride = 2 * KC * 64;
    const __nv_bfloat16* Bblk = Bimg + (size_t)cb0 * stride;
    const int NC = 3 * KC;

    float acc[2][8][4];
    #pragma unroll
    for (int mt = 0; mt < 2; mt++)
        #pragma unroll
        for (int nt = 0; nt < 8; nt++)
            #pragma unroll
            for (int q = 0; q < 4; q++) acc[mt][nt][q] = 0.0f;

    auto load_chunk = [&](int c, int b) {
        int cA = (c < 2 * KC) ? c : c - 2 * KC;
        int cB = (c < KC) ? c : c - KC;
        const int base = b * CHUNKE;
        const __nv_bfloat16* Ab = Aimg + (size_t)arow0 * stride + cA * 64;
        for (int v = tid; v < TM * 8; v += 512) {
            int r = v >> 3, s = v & 7;
            cp_async16(sbase + (base + r * LDS + s * 8) * 2, Ab + (size_t)r * stride + s * 8);
        }
        const __nv_bfloat16* Bb = Bblk + cB * 64;
        for (int v = tid; v < TN * 8; v += 512) {
            int r = v >> 3, s = v & 7;
            cp_async16(sbase + (base + TM * LDS + r * LDS + s * 8) * 2, Bb + (size_t)r * stride + s * 8);
        }
        cp_commit();
    };

    auto compute_chunk = [&](int b) {
        const uint32_t aBase = sbase + (b * CHUNKE) * 2;
        const uint32_t bBase = aBase + TM * LDS * 2;
        #pragma unroll
        for (int ks = 0; ks < 4; ks++) {
            uint32_t afr[2][4];
            #pragma unroll
            for (int mt = 0; mt < 2; mt++) {
                uint32_t ad = aBase +
                    ((wm0 + mt * 16 + (lane & 15)) * LDS + ks * 16 + (lane >> 4) * 8) * 2;
                ldsm_x4(afr[mt], ad);
            }
            uint32_t bfr[4][4];
            #pragma unroll
            for (int ntp = 0; ntp < 4; ntp++) {
                int n = wn0 + ntp * 16 + (lane & 7) + ((lane >> 4) << 3);
                int koff = ks * 16 + ((lane >> 3) & 1) * 8;
                ldsm_x4(bfr[ntp], bBase + (n * LDS + koff) * 2);
            }
            #pragma unroll
            for (int mt = 0; mt < 2; mt++)
                #pragma unroll
                for (int ntp = 0; ntp < 4; ntp++) {
                    mma_bf16(acc[mt][ntp * 2 + 0], afr[mt], bfr[ntp][0], bfr[ntp][1]);
                    mma_bf16(acc[mt][ntp * 2 + 1], afr[mt], bfr[ntp][2], bfr[ntp][3]);
                }
        }
    };

    // ---- pipelined main loop: kg0 even chunks, kg1 odd chunks ------------
    load_chunk(0, 0);
    load_chunk(1, 1);
    for (int p = 0; p < NC; p += 2) {
        if (p + 3 < NC) {
            load_chunk(p + 2, (p + 2) & 3);
            load_chunk(p + 3, (p + 3) & 3);
            asm volatile("cp.async.wait_group 2;");
        } else {
            asm volatile("cp.async.wait_group 0;");
        }
        __syncthreads();
        compute_chunk((p + kg) & 3);
        __syncthreads();
    }

    // ---- split-K reduction: kg1 -> smem, kg0 adds ------------------------
    float* sred = (float*)smem;
    if (kg == 1) {
        float* dst = sred + ((size_t)(wl * 32 + lane) * 64);
        int idx = 0;
        #pragma unroll
        for (int mt = 0; mt < 2; mt++)
            #pragma unroll
            for (int nt = 0; nt < 8; nt++)
                #pragma unroll
                for (int q = 0; q < 4; q++) dst[idx++] = acc[mt][nt][q];
    }
    __syncthreads();
    if (kg == 0) {
        const float* s = sred + ((size_t)(wl * 32 + lane) * 64);
        int idx = 0;
        #pragma unroll
        for (int mt = 0; mt < 2; mt++)
            #pragma unroll
            for (int nt = 0; nt < 8; nt++)
                #pragma unroll
                for (int q = 0; q < 4; q++) acc[mt][nt][q] += s[idx++];
    }

    // ---- epilogue --------------------------------------------------------
    if (MODE == 0) {
        if (kg == 0) {
            uint32_t* H32 = (uint32_t*)Himg;
            #pragma unroll
            for (int mt = 0; mt < 2; mt++) {
                #pragma unroll
                for (int nt = 0; nt < 8; nt++) {
                    int rl = wm0 + mt * 16 + (lane >> 2);
                    int j  = cb0 + wn0 + (nt >> 1) * 16 + (nt & 1) * 8 + (lane & 3) * 2;
                    #pragma unroll
                    for (int hrow = 0; hrow < 2; hrow++) {
                        int grow = grow0 + rl + hrow * 8;
                        int op = g_op_l[grow];
                        float bj0 = __ldg(&bvec[op * 512 + j]);
                        float bj1 = __ldg(&bvec[op * 512 + j + 1]);
                        float h0 = gelu_exact(acc[mt][nt][hrow * 2 + 0] + bj0);
                        float h1 = gelu_exact(acc[mt][nt][hrow * 2 + 1] + bj1);
                        __nv_bfloat16 h0h = __float2bfloat16(h0);
                        __nv_bfloat16 h1h = __float2bfloat16(h1);
                        __nv_bfloat16 h0l = __float2bfloat16(h0 - __bfloat162float(h0h));
                        __nv_bfloat16 h1l = __float2bfloat16(h1 - __bfloat162float(h1h));
                        uint32_t hw = (uint32_t)__bfloat16_as_ushort(h1h) << 16 | __bfloat16_as_ushort(h0h);
                        uint32_t lw = (uint32_t)__bfloat16_as_ushort(h1l) << 16 | __bfloat16_as_ushort(h0l);
                        size_t rb = (size_t)grow * 512;
                        H32[rb + (j >> 1)]       = hw;
                        H32[rb + 256 + (j >> 1)] = lw;
                    }
                }
            }
        }
    } else {
        float* sy = (float*)(smem + 65536);            // [64][257]
        if (kg == 0) {
            #pragma unroll
            for (int mt = 0; mt < 2; mt++) {
                #pragma unroll
                for (int nt = 0; nt < 8; nt++) {
                    int rl  = wm0 + mt * 16 + (lane >> 2);
                    int col = wn0 + (nt >> 1) * 16 + (nt & 1) * 8 + (lane & 3) * 2;
                    float b0 = __ldg(&bvec[col]);
                    float b1 = __ldg(&bvec[col + 1]);
                    #pragma unroll
                    for (int hrow = 0; hrow < 2; hrow++) {
                        int r = rl + hrow * 8;
                        int grow = grow0 + r;
                        float r0 = __ldg(&Rres[(size_t)grow * D + col]);
                        float r1 = __ldg(&Rres[(size_t)grow * D + col + 1]);
                        sy[r * 257 + col]     = acc[mt][nt][hrow * 2 + 0] + b0 + r0;
                        sy[r * 257 + col + 1] = acc[mt][nt][hrow * 2 + 1] + b1 + r1;
                    }
                }
            }
        }
        __syncthreads();
        #pragma unroll
        for (int rr = 0; rr < 4; rr++) {
            int rn = wid * 4 + rr;
            int grow = grow0 + rn;
            float vals[8];
            float s = 0.0f, s2 = 0.0f;
            #pragma unroll
            for (int k = 0; k < 8; k++) {
                float v = sy[rn * 257 + lane + k * 32];
                vals[k] = v; s += v; s2 = fmaf(v, v, s2);
            }
            #pragma unroll
            for (int off = 16; off > 0; off >>= 1) {
                s  += __shfl_xor_sync(0xFFFFFFFF, s, off);
                s2 += __shfl_xor_sync(0xFFFFFFFF, s2, off);
            }
            float mu  = s * (1.0f / 256.0f);
            float var = s2 * (1.0f / 256.0f) - mu * mu;
            float inv = rsqrtf(var + 1e-5f);
            float* dst = (MODE == 1) ? outp + (size_t)g_nodes_l[grow] * D
                                     : outp + (size_t)grow * D;
            #pragma unroll
            for (int k = 0; k < 8; k++) {
                int d = lane + k * 32;
                dst[d] = (vals[k] - mu) * inv * __ldg(&gamma[d]) + __ldg(&beta[d]);
            }
        }
    }
}

// ===========================================================================
extern "C" void kernel_launch(void* const* d_in, const int* in_sizes, int n_in,
                              void* d_out, int out_size) {
    const int*   comp_ids   = (const int*)d_in[0];
    const int*   op_ids     = (const int*)d_in[1];
    const int*   lc         = (const int*)d_in[2];
    const int*   rc         = (const int*)d_in[3];
    const int*   tc         = (const int*)d_in[4];
    const int*   lvl2       = (const int*)d_in[5];
    const int*   lvl1       = (const int*)d_in[6];
    const int*   lvl0       = (const int*)d_in[7];
    const float* comp_table = (const float*)d_in[8];
    const float* op_table   = (const float*)d_in[9];
    const float* W1b        = (const float*)d_in[10];
    const float* b1b        = (const float*)d_in[11];
    const float* W2b        = (const float*)d_in[12];
    const float* b2b        = (const float*)d_in[13];
    const float* W1t        = (const float*)d_in[14];
    const float* b1t        = (const float*)d_in[15];
    const float* W2t        = (const float*)d_in[16];
    const float* b2t        = (const float*)d_in[17];
    const float* gamma      = (const float*)d_in[18];
    const float* beta       = (const float*)d_in[19];
    float* out = (float*)d_out;

    float* p_gnodes;  cudaGetSymbolAddress((void**)&p_gnodes, g_nodes);
    float* p_R;       cudaGetSymbolAddress((void**)&p_R, g_R);
    float* p_opb_b;   cudaGetSymbolAddress((void**)&p_opb_b, g_opb_b);
    float* p_opb_t;   cudaGetSymbolAddress((void**)&p_opb_t, g_opb_t);
    __nv_bfloat16 *p_Xt, *p_Xb, *p_H, *p_W1b, *p_W1t, *p_W2b, *p_W2t;
    cudaGetSymbolAddress((void**)&p_Xt,  g_Xt_img);
    cudaGetSymbolAddress((void**)&p_Xb,  g_Xb_img);
    cudaGetSymbolAddress((void**)&p_H,   g_H_img);
    cudaGetSymbolAddress((void**)&p_W1b, g_W1b_img);
    cudaGetSymbolAddress((void**)&p_W1t, g_W1t_img);
    cudaGetSymbolAddress((void**)&p_W2b, g_W2b_img);
    cudaGetSymbolAddress((void**)&p_W2t, g_W2t_img);

    const int SMEM0 = 4 * (128 + 128) * LDS * 2;   // 147456
    const int SMEM1 = 4 * (64 + 256) * LDS * 2;    // 184320
    cudaFuncSetAttribute(mma_kernel<0>, cudaFuncAttributeMaxDynamicSharedMemorySize, SMEM0);
    cudaFuncSetAttribute(mma_kernel<1>, cudaFuncAttributeMaxDynamicSharedMemorySize, SMEM1);
    cudaFuncSetAttribute(mma_kernel<2>, cudaFuncAttributeMaxDynamicSharedMemorySize, SMEM1);

    // 0) all setup in one launch
    setup_kernel<<<3648, 256>>>(W1b, b1b, W2b, W1t, b1t, W2t, op_table);

    // 1) lvl2 (tern rows 0..4095, bin rows 4096..16383), leaf children
    prep_kernel<true><<<16384, 256>>>(lvl2, 4, 4096, op_ids, lc, rc, tc, comp_ids, comp_table);
    mma_kernel<0><<<dim3(128, 4), 512, SMEM0>>>(
        p_Xt, p_W1t, p_opb_t, 12, 32,
        p_Xb, p_W1b, p_opb_b, 8,
        p_H, nullptr, gamma, beta, nullptr);
    mma_kernel<1><<<256, 512, SMEM1>>>(
        p_H, p_W2t, b2t, 8, 64,
        nullptr, p_W2b, b2b, 8,
        nullptr, p_R, gamma, beta, p_gnodes);

    // 2) lvl1 (all binary)
    prep_kernel<false><<<8192, 256>>>(lvl1, 2, 0, op_ids, lc, rc, tc, comp_ids, comp_table);
    mma_kernel<0><<<dim3(64, 4), 512, SMEM0>>>(
        p_Xb, p_W1b, p_opb_b, 8, 0,
        p_Xb, p_W1b, p_opb_b, 8,
        p_H, nullptr, gamma, beta, nullptr);
    mma_kernel<1><<<128, 512, SMEM1>>>(
        p_H, p_W2b, b2b, 8, 0,
        nullptr, p_W2b, b2b, 8,
        nullptr, p_R, gamma, beta, p_gnodes);

    // 3) lvl0 (all binary) -> dense out
    prep_kernel<false><<<4096, 256>>>(lvl0, 1, 0, op_ids, lc, rc, tc, comp_ids, comp_table);
    mma_kernel<0><<<dim3(32, 4), 512, SMEM0>>>(
        p_Xb, p_W1b, p_opb_b, 8, 0,
        p_Xb, p_W1b, p_opb_b, 8,
        p_H, nullptr, gamma, beta, nullptr);
    mma_kernel<2><<<64, 512, SMEM1>>>(
        p_H, p_W2b, b2b, 8, 0,
        nullptr, p_W2b, b2b, 8,
        nullptr, p_R, gamma, beta, out);

    (void)n_in; (void)out_size;
}

// round 12
// speedup vs baseline: 1.5626x; 1.5626x over previous
#include <cuda_runtime.h>
#include <cuda_fp16.h>
#include <cstdint>
#include <math.h>

#define D 256
#define LDS 72   // smem row stride in fp16 elems (64 data + 8 pad)

// ===========================================================================
// Static device scratch (unified global row space per level: tern rows first)
// ===========================================================================
__device__ float g_nodes[65536 * D];
__device__ __half g_Xt_img[4096  * 768];       // ternary X, single fp16
__device__ __half g_Xb_img[12288 * 512];       // binary  X, single fp16
__device__ __half g_H_img [16384 * 512];       // H, single fp16, global rows
__device__ float g_R[16384 * D];
__device__ int   g_nodes_l[16384];
__device__ int   g_op_l[16384];
__device__ __half g_W1b_img[512 * 1024];       // [N=512][whi512|wlo512]
__device__ __half g_W1t_img[512 * 1536];       // [N=512][whi768|wlo768]
__device__ __half g_W2b_img[256 * 1024];
__device__ __half g_W2t_img[256 * 1024];
__device__ float g_opb_b[16 * 512];
__device__ float g_opb_t[16 * 512];

// ===========================================================================
// Helpers (sm_80-era PTX only)
// ===========================================================================
__device__ __forceinline__ uint32_t smem_u32(const void* p) {
    uint32_t a;
    asm("{ .reg .u64 t; cvta.to.shared.u64 t, %1; cvt.u32.u64 %0, t; }" : "=r"(a) : "l"(p));
    return a;
}
__device__ __forceinline__ void cp_async16(uint32_t saddr, const void* gaddr) {
    asm volatile("cp.async.cg.shared.global [%0], [%1], 16;" :: "r"(saddr), "l"(gaddr));
}
__device__ __forceinline__ void cp_commit() {
    asm volatile("cp.async.commit_group;");
}
__device__ __forceinline__ void ldsm_x4(uint32_t* r, uint32_t addr) {
    asm volatile("ldmatrix.sync.aligned.m8n8.x4.shared.b16 {%0,%1,%2,%3}, [%4];"
                 : "=r"(r[0]), "=r"(r[1]), "=r"(r[2]), "=r"(r[3]) : "r"(addr));
}
__device__ __forceinline__ void mma_f16(float* c, const uint32_t* a, uint32_t b0, uint32_t b1) {
    asm volatile("mma.sync.aligned.m16n8k16.row.col.f32.f16.f16.f32 "
                 "{%0,%1,%2,%3}, {%4,%5,%6,%7}, {%8,%9}, {%0,%1,%2,%3};"
                 : "+f"(c[0]), "+f"(c[1]), "+f"(c[2]), "+f"(c[3])
                 : "r"(a[0]), "r"(a[1]), "r"(a[2]), "r"(a[3]), "r"(b0), "r"(b1));
}
__device__ __forceinline__ float gelu_exact(float a) {
    return 0.5f * a * (1.0f + erff(a * 0.70710678118654752f));
}

// ===========================================================================
// Combined setup: weight images [whi(K)|wlo(K)] per output row + op tables
// ===========================================================================
__device__ __forceinline__ void wprep_body(const float* __restrict__ W,
                                           __half* __restrict__ img,
                                           int K, int N, int idx) {
    if (idx >= K * N) return;
    int k = idx / N, n = idx % N;
    float v = W[idx];
    __half hi = __float2half_rn(v);
    __half lo = __float2half_rn(v - __half2float(hi));
    size_t base = (size_t)n * 2 * K;
    img[base + k] = hi;
    img[base + K + k] = lo;
}
__device__ __forceinline__ void opproj_body(const float* __restrict__ op_table,
                                            const float* __restrict__ W1,
                                            const float* __restrict__ b1,
                                            float* __restrict__ outb, int idx) {
    int o = idx >> 9, j = idx & 511;
    float s = b1[j];
    const float* oe = op_table + o * D;
    #pragma unroll 8
    for (int k = 0; k < D; k++)
        s = fmaf(oe[k], W1[(size_t)k * 512 + j], s);
    outb[idx] = s;
}
__global__ void setup_kernel(const float* __restrict__ W1b, const float* __restrict__ b1b,
                             const float* __restrict__ W2b,
                             const float* __restrict__ W1t, const float* __restrict__ b1t,
                             const float* __restrict__ W2t,
                             const float* __restrict__ op_table) {
    int b = blockIdx.x, tid = threadIdx.x;
    if (b < 1024)      wprep_body(W1b + 256 * 512, g_W1b_img, 512, 512, b * 256 + tid);
    else if (b < 2560) wprep_body(W1t + 256 * 512, g_W1t_img, 768, 512, (b - 1024) * 256 + tid);
    else if (b < 3072) wprep_body(W2b, g_W2b_img, 512, 256, (b - 2560) * 256 + tid);
    else if (b < 3584) wprep_body(W2t, g_W2t_img, 512, 256, (b - 3072) * 256 + tid);
    else if (b < 3616) opproj_body(op_table, W1b, b1b, g_opb_b, (b - 3584) * 256 + tid);
    else               opproj_body(op_table, W1t, b1t, g_opb_t, (b - 3616) * 256 + tid);
}

// ===========================================================================
// X prep (merged tern/bin): gg < tern_cnt -> ternary row gg of Xt (width 768);
// else binary row (gg - tern_cnt) of Xb (width 512). Global row = gg.
// ===========================================================================
template <bool LEAF>
__global__ void prep_kernel(const int* __restrict__ lvl_idx, int phases, int tern_cnt,
                            const int* __restrict__ op_ids,
                            const int* __restrict__ lc, const int* __restrict__ rc,
                            const int* __restrict__ tc,
                            const int* __restrict__ comp_ids,
                            const float* __restrict__ comp_table) {
    int gg = blockIdx.x;
    bool tern = gg < tern_cnt;
    __shared__ int sids[3];
    int d = threadIdx.x;
    if (d == 0) {
        int pos = (gg & 4095) * phases + (gg >> 12);
        int node = lvl_idx[pos];
        int l = lc[node], r = rc[node];
        sids[0] = LEAF ? comp_ids[l] : l;
        sids[1] = LEAF ? comp_ids[r] : r;
        if (tern) { int t = tc[node]; sids[2] = LEAF ? comp_ids[t] : t; }
        g_nodes_l[gg] = node;
        g_op_l[gg] = op_ids[node];
    }
    __syncthreads();
    const float* src = LEAF ? comp_table : g_nodes;
    float lev = src[(size_t)sids[0] * D + d];
    float rev = src[(size_t)sids[1] * D + d];
    if (tern) {
        float tev = src[(size_t)sids[2] * D + d];
        __half* row = g_Xt_img + (size_t)gg * 768;
        row[d]           = __float2half_rn(lev);
        row[256 + d]     = __float2half_rn(rev);
        row[512 + d]     = __float2half_rn(tev);
        g_R[(size_t)gg * D + d] = (lev + rev + tev) * (1.0f / 3.0f);
    } else {
        __half* row = g_Xb_img + (size_t)(gg - tern_cnt) * 512;
        row[d]       = __float2half_rn(lev);
        row[256 + d] = __float2half_rn(rev);
        g_R[(size_t)gg * D + d] = lev + rev;
    }
}

// ===========================================================================
// HMMA GEMM fp16, 256 threads, double-buffered. Logical K = 2 passes:
//   pass0: A x Bhi ; pass1: A x Blo.  srcA = c<KC ? c : c-KC ; srcB = c.
// A stride = KC*64; B stride = 2*KC*64.
// MODE 0: 128x128 tile, segment by blockIdx.x<nblk0 (tern/bin), opbias+gelu -> H (fp16).
// MODE 1: 64x256 tile, segment by row, bias+residual+LN -> scatter g_nodes.
// MODE 2: like 1 but dense out[row].
// ===========================================================================
template <int MODE>
__global__ void __launch_bounds__(256, 2)
mma_kernel(const __nv_half* __restrict__ A0, const __nv_half* __restrict__ B0,
           const float* __restrict__ bias0, int KC0, int nblk0,
           const __nv_half* __restrict__ A1, const __nv_half* __restrict__ B1,
           const float* __restrict__ bias1, int KC1,
           __half* __restrict__ Himg, const float* __restrict__ Rres,
           const float* __restrict__ gamma, const float* __restrict__ beta,
           float* __restrict__ outp) {
    constexpr int TM = (MODE == 0) ? 128 : 64;
    constexpr int TN = (MODE == 0) ? 128 : 256;
    constexpr int CHUNKE = (TM + TN) * LDS;     // fp16 elems per buffer
    constexpr int WM = TM / 32;

    extern __shared__ char smem[];
    const uint32_t sbase = smem_u32(smem);
    const int tid = threadIdx.x, wid = tid >> 5, lane = tid & 31;
    const int warp_m = wid & (WM - 1), warp_n = wid / WM;
    const int wm0 = warp_m * 32, wn0 = warp_n * 64;
    const int bx = blockIdx.x;
    const int cb0 = (MODE == 0) ? blockIdx.y * 128 : 0;

    int KC, grow0, arow0;
    const __half *Aimg, *Bimg;
    const float* bvec;
    if (MODE == 0) {
        if (bx < nblk0) { KC = KC0; Aimg = A0; Bimg = B0; bvec = bias0; arow0 = bx * 128; grow0 = arow0; }
        else { KC = KC1; Aimg = A1; Bimg = B1; bvec = bias1;
               arow0 = (bx - nblk0) * 128; grow0 = nblk0 * 128 + arow0; }
    } else {
        grow0 = bx * 64; arow0 = grow0; Aimg = A0;
        if (bx < nblk0) { KC = KC0; Bimg = B0; bvec = bias0; }
        else            { KC = KC1; Bimg = B1; bvec = bias1; }
    }
    const int strideA = KC * 64;
    const int strideB = 2 * KC * 64;
    const __half* Bblk = Bimg + (size_t)cb0 * strideB;
    const int NC = 2 * KC;

    float acc[2][8][4];
    #pragma unroll
    for (int mt = 0; mt < 2; mt++)
        #pragma unroll
        for (int nt = 0; nt < 8; nt++)
            #pragma unroll
            for (int q = 0; q < 4; q++) acc[mt][nt][q] = 0.0f;

    auto load_chunk = [&](int c, int b) {
        int cA = (c < KC) ? c : c - KC;
        const int base = b * CHUNKE;
        const __half* Ab = Aimg + (size_t)arow0 * strideA + cA * 64;
        #pragma unroll
        for (int v = tid; v < TM * 8; v += 256) {
            int r = v >> 3, s = v & 7;
            cp_async16(sbase + (base + r * LDS + s * 8) * 2, Ab + (size_t)r * strideA + s * 8);
        }
        const __half* Bb = Bblk + c * 64;
        #pragma unroll
        for (int v = tid; v < TN * 8; v += 256) {
            int r = v >> 3, s = v & 7;
            cp_async16(sbase + (base + TM * LDS + r * LDS + s * 8) * 2, Bb + (size_t)r * strideB + s * 8);
        }
        cp_commit();
    };

    load_chunk(0, 0);
    for (int c = 0; c < NC; c++) {
        const int b = c & 1;
        if (c + 1 < NC) {
            load_chunk(c + 1, (c + 1) & 1);
            asm volatile("cp.async.wait_group 1;");
        } else {
            asm volatile("cp.async.wait_group 0;");
        }
        __syncthreads();

        const uint32_t aBase = sbase + (b * CHUNKE) * 2;
        const uint32_t bBase = aBase + TM * LDS * 2;
        #pragma unroll
        for (int ks = 0; ks < 4; ks++) {
            uint32_t afr[2][4];
            #pragma unroll
            for (int mt = 0; mt < 2; mt++) {
                uint32_t ad = aBase +
                    ((wm0 + mt * 16 + (lane & 15)) * LDS + ks * 16 + (lane >> 4) * 8) * 2;
                ldsm_x4(afr[mt], ad);
            }
            uint32_t bfr[4][4];
            #pragma unroll
            for (int ntp = 0; ntp < 4; ntp++) {
                int n = wn0 + ntp * 16 + (lane & 7) + ((lane >> 4) << 3);
                int koff = ks * 16 + ((lane >> 3) & 1) * 8;
                ldsm_x4(bfr[ntp], bBase + (n * LDS + koff) * 2);
            }
            #pragma unroll
            for (int mt = 0; mt < 2; mt++)
                #pragma unroll
                for (int ntp = 0; ntp < 4; ntp++) {
                    mma_f16(acc[mt][ntp * 2 + 0], afr[mt], bfr[ntp][0], bfr[ntp][1]);
                    mma_f16(acc[mt][ntp * 2 + 1], afr[mt], bfr[ntp][2], bfr[ntp][3]);
                }
        }
        __syncthreads();
    }

    // ---- epilogue --------------------------------------------------------
    if (MODE == 0) {
        uint32_t* H32 = (uint32_t*)Himg;
        #pragma unroll
        for (int mt = 0; mt < 2; mt++) {
            #pragma unroll
            for (int nt = 0; nt < 8; nt++) {
                int rl = wm0 + mt * 16 + (lane >> 2);
                int j  = cb0 + wn0 + (nt >> 1) * 16 + (nt & 1) * 8 + (lane & 3) * 2;
                #pragma unroll
                for (int hrow = 0; hrow < 2; hrow++) {
                    int grow = grow0 + rl + hrow * 8;
                    int op = g_op_l[grow];
                    float bj0 = __ldg(&bvec[op * 512 + j]);
                    float bj1 = __ldg(&bvec[op * 512 + j + 1]);
                    float h0 = gelu_exact(acc[mt][nt][hrow * 2 + 0] + bj0);
                    float h1 = gelu_exact(acc[mt][nt][hrow * 2 + 1] + bj1);
                    __half hh0 = __float2half_rn(h0);
                    __half hh1 = __float2half_rn(h1);
                    uint32_t hw = (uint32_t)__half_as_ushort(hh1) << 16 | __half_as_ushort(hh0);
                    H32[(size_t)grow * 256 + (j >> 1)] = hw;   // 512 fp16 / 2 per row
                }
            }
        }
    } else {
        float* sy = (float*)smem;                        // [64][257], buffers dead
        #pragma unroll
        for (int mt = 0; mt < 2; mt++) {
            #pragma unroll
            for (int nt = 0; nt < 8; nt++) {
                int rl  = wm0 + mt * 16 + (lane >> 2);
                int col = wn0 + (nt >> 1) * 16 + (nt & 1) * 8 + (lane & 3) * 2;
                float b0 = __ldg(&bvec[col]);
                float b1 = __ldg(&bvec[col + 1]);
                #pragma unroll
                for (int hrow = 0; hrow < 2; hrow++) {
                    int r = rl + hrow * 8;
                    int grow = grow0 + r;
                    float r0 = __ldg(&Rres[(size_t)grow * D + col]);
                    float r1 = __ldg(&Rres[(size_t)grow * D + col + 1]);
                    sy[r * 257 + col]     = acc[mt][nt][hrow * 2 + 0] + b0 + r0;
                    sy[r * 257 + col + 1] = acc[mt][nt][hrow * 2 + 1] + b1 + r1;
                }
            }
        }
        __syncthreads();
        #pragma unroll
        for (int rr = 0; rr < 8; rr++) {
            int rn = wid * 8 + rr;
            int grow = grow0 + rn;
            float vals[8];
            float s = 0.0f, s2 = 0.0f;
            #pragma unroll
            for (int k = 0; k < 8; k++) {
                float v = sy[rn * 257 + lane + k * 32];
                vals[k] = v; s += v; s2 = fmaf(v, v, s2);
            }
            #pragma unroll
            for (int off = 16; off > 0; off >>= 1) {
                s  += __shfl_xor_sync(0xFFFFFFFF, s, off);
                s2 += __shfl_xor_sync(0xFFFFFFFF, s2, off);
            }
            float mu  = s * (1.0f / 256.0f);
            float var = s2 * (1.0f / 256.0f) - mu * mu;
            float inv = rsqrtf(var + 1e-5f);
            float* dst = (MODE == 1) ? outp + (size_t)g_nodes_l[grow] * D
                                     : outp + (size_t)grow * D;
            #pragma unroll
            for (int k = 0; k < 8; k++) {
                int d = lane + k * 32;
                dst[d] = (vals[k] - mu) * inv * __ldg(&gamma[d]) + __ldg(&beta[d]);
            }
        }
    }
}

// ===========================================================================
extern "C" void kernel_launch(void* const* d_in, const int* in_sizes, int n_in,
                              void* d_out, int out_size) {
    const int*   comp_ids   = (const int*)d_in[0];
    const int*   op_ids     = (const int*)d_in[1];
    const int*   lc         = (const int*)d_in[2];
    const int*   rc         = (const int*)d_in[3];
    const int*   tc         = (const int*)d_in[4];
    const int*   lvl2       = (const int*)d_in[5];
    const int*   lvl1       = (const int*)d_in[6];
    const int*   lvl0       = (const int*)d_in[7];
    const float* comp_table = (const float*)d_in[8];
    const float* op_table   = (const float*)d_in[9];
    const float* W1b        = (const float*)d_in[10];
    const float* b1b        = (const float*)d_in[11];
    const float* W2b        = (const float*)d_in[12];
    const float* b2b        = (const float*)d_in[13];
    const float* W1t        = (const float*)d_in[14];
    const float* b1t        = (const float*)d_in[15];
    const float* W2t        = (const float*)d_in[16];
    const float* b2t        = (const float*)d_in[17];
    const float* gamma      = (const float*)d_in[18];
    const float* beta       = (const float*)d_in[19];
    float* out = (float*)d_out;

    float* p_gnodes;  cudaGetSymbolAddress((void**)&p_gnodes, g_nodes);
    float* p_R;       cudaGetSymbolAddress((void**)&p_R, g_R);
    float* p_opb_b;   cudaGetSymbolAddress((void**)&p_opb_b, g_opb_b);
    float* p_opb_t;   cudaGetSymbolAddress((void**)&p_opb_t, g_opb_t);
    __half *p_Xt, *p_Xb, *p_H, *p_W1b, *p_W1t, *p_W2b, *p_W2t;
    cudaGetSymbolAddress((void**)&p_Xt,  g_Xt_img);
    cudaGetSymbolAddress((void**)&p_Xb,  g_Xb_img);
    cudaGetSymbolAddress((void**)&p_H,   g_H_img);
    cudaGetSymbolAddress((void**)&p_W1b, g_W1b_img);
    cudaGetSymbolAddress((void**)&p_W1t, g_W1t_img);
    cudaGetSymbolAddress((void**)&p_W2b, g_W2b_img);
    cudaGetSymbolAddress((void**)&p_W2t, g_W2t_img);

    const int SMEM0 = 2 * (128 + 128) * LDS * 2;   // 73,728
    const int SMEM1 = 2 * (64 + 256) * LDS * 2;    // 92,160
    cudaFuncSetAttribute(mma_kernel<0>, cudaFuncAttributeMaxDynamicSharedMemorySize, SMEM0);
    cudaFuncSetAttribute(mma_kernel<1>, cudaFuncAttributeMaxDynamicSharedMemorySize, SMEM1);
    cudaFuncSetAttribute(mma_kernel<2>, cudaFuncAttributeMaxDynamicSharedMemorySize, SMEM1);

    // 0) all setup in one launch
    setup_kernel<<<3648, 256>>>(W1b, b1b, W2b, W1t, b1t, W2t, op_table);

    // 1) lvl2 (tern rows 0..4095, bin rows 4096..16383), leaf children
    prep_kernel<true><<<16384, 256>>>(lvl2, 4, 4096, op_ids, lc, rc, tc, comp_ids, comp_table);
    mma_kernel<0><<<dim3(128, 4), 256, SMEM0>>>(
        p_Xt, p_W1t, p_opb_t, 12, 32,
        p_Xb, p_W1b, p_opb_b, 8,
        p_H, nullptr, gamma, beta, nullptr);
    mma_kernel<1><<<256, 256, SMEM1>>>(
        p_H, p_W2t, b2t, 8, 64,
        nullptr, p_W2b, b2b, 8,
        nullptr, p_R, gamma, beta, p_gnodes);

    // 2) lvl1 (all binary)
    prep_kernel<false><<<8192, 256>>>(lvl1, 2, 0, op_ids, lc, rc, tc, comp_ids, comp_table);
    mma_kernel<0><<<dim3(64, 4), 256, SMEM0>>>(
        p_Xb, p_W1b, p_opb_b, 8, 0,
        p_Xb, p_W1b, p_opb_b, 8,
        p_H, nullptr, gamma, beta, nullptr);
    mma_kernel<1><<<128, 256, SMEM1>>>(
        p_H, p_W2b, b2b, 8, 0,
        nullptr, p_W2b, b2b, 8,
        nullptr, p_R, gamma, beta, p_gnodes);

    // 3) lvl0 (all binary) -> dense out
    prep_kernel<false><<<4096, 256>>>(lvl0, 1, 0, op_ids, lc, rc, tc, comp_ids, comp_table);
    mma_kernel<0><<<dim3(32, 4), 256, SMEM0>>>(
        p_Xb, p_W1b, p_opb_b, 8, 0,
        p_Xb, p_W1b, p_opb_b, 8,
        p_H, nullptr, gamma, beta, nullptr);
    mma_kernel<2><<<64, 256, SMEM1>>>(
        p_H, p_W2b, b2b, 8, 0,
        nullptr, p_W2b, b2b, 8,
        nullptr, p_R, gamma, beta, out);

    (void)n_in; (void)out_size;
}

// round 13
// speedup vs baseline: 2.2221x; 1.4220x over previous
#include <cuda_runtime.h>
#include <cuda_fp16.h>
#include <cstdint>
#include <math.h>

#define D 256
#define LDS 72   // smem row stride in fp16 elems (64 data + 8 pad)

// ===========================================================================
// Static device scratch (unified global row space per level: tern rows first)
// ===========================================================================
__device__ float g_nodes[65536 * D];
__device__ __half g_Xt_img[4096  * 768];       // ternary X, fp16
__device__ __half g_Xb_img[12288 * 512];       // binary  X, fp16
__device__ __half g_H_img [16384 * 512];       // H, fp16, global rows
__device__ float g_R[16384 * D];
__device__ int   g_nodes_l[16384];
__device__ int   g_op_l[16384];
__device__ __half g_W1b_img[512 * 512];        // [N=512][K=512] fp16
__device__ __half g_W1t_img[512 * 768];        // [N=512][K=768] fp16
__device__ __half g_W2b_img[256 * 512];
__device__ __half g_W2t_img[256 * 512];
__device__ float g_opb_b[16 * 512];
__device__ float g_opb_t[16 * 512];

// ===========================================================================
// Helpers (sm_80-era PTX only)
// ===========================================================================
__device__ __forceinline__ uint32_t smem_u32(const void* p) {
    uint32_t a;
    asm("{ .reg .u64 t; cvta.to.shared.u64 t, %1; cvt.u32.u64 %0, t; }" : "=r"(a) : "l"(p));
    return a;
}
__device__ __forceinline__ void cp_async16(uint32_t saddr, const void* gaddr) {
    asm volatile("cp.async.cg.shared.global [%0], [%1], 16;" :: "r"(saddr), "l"(gaddr));
}
__device__ __forceinline__ void cp_commit() {
    asm volatile("cp.async.commit_group;");
}
__device__ __forceinline__ void ldsm_x4(uint32_t* r, uint32_t addr) {
    asm volatile("ldmatrix.sync.aligned.m8n8.x4.shared.b16 {%0,%1,%2,%3}, [%4];"
                 : "=r"(r[0]), "=r"(r[1]), "=r"(r[2]), "=r"(r[3]) : "r"(addr));
}
__device__ __forceinline__ void mma_f16(float* c, const uint32_t* a, uint32_t b0, uint32_t b1) {
    asm volatile("mma.sync.aligned.m16n8k16.row.col.f32.f16.f16.f32 "
                 "{%0,%1,%2,%3}, {%4,%5,%6,%7}, {%8,%9}, {%0,%1,%2,%3};"
                 : "+f"(c[0]), "+f"(c[1]), "+f"(c[2]), "+f"(c[3])
                 : "r"(a[0]), "r"(a[1]), "r"(a[2]), "r"(a[3]), "r"(b0), "r"(b1));
}
__device__ __forceinline__ float gelu_exact(float a) {
    return 0.5f * a * (1.0f + erff(a * 0.70710678118654752f));
}

// ===========================================================================
// Combined setup: weight images [N][K] fp16 + exact op-projection tables
// ===========================================================================
__device__ __forceinline__ void wprep_body(const float* __restrict__ W,
                                           __half* __restrict__ img,
                                           int K, int N, int idx) {
    if (idx >= K * N) return;
    int k = idx / N, n = idx % N;
    img[(size_t)n * K + k] = __float2half_rn(W[idx]);
}
__device__ __forceinline__ void opproj_body(const float* __restrict__ op_table,
                                            const float* __restrict__ W1,
                                            const float* __restrict__ b1,
                                            float* __restrict__ outb, int idx) {
    int o = idx >> 9, j = idx & 511;
    float s = b1[j];
    const float* oe = op_table + o * D;
    #pragma unroll 8
    for (int k = 0; k < D; k++)
        s = fmaf(oe[k], W1[(size_t)k * 512 + j], s);
    outb[idx] = s;
}
__global__ void setup_kernel(const float* __restrict__ W1b, const float* __restrict__ b1b,
                             const float* __restrict__ W2b,
                             const float* __restrict__ W1t, const float* __restrict__ b1t,
                             const float* __restrict__ W2t,
                             const float* __restrict__ op_table) {
    int b = blockIdx.x, tid = threadIdx.x;
    if (b < 1024)      wprep_body(W1b + 256 * 512, g_W1b_img, 512, 512, b * 256 + tid);
    else if (b < 2560) wprep_body(W1t + 256 * 512, g_W1t_img, 768, 512, (b - 1024) * 256 + tid);
    else if (b < 3072) wprep_body(W2b, g_W2b_img, 512, 256, (b - 2560) * 256 + tid);
    else if (b < 3584) wprep_body(W2t, g_W2t_img, 512, 256, (b - 3072) * 256 + tid);
    else if (b < 3616) opproj_body(op_table, W1b, b1b, g_opb_b, (b - 3584) * 256 + tid);
    else               opproj_body(op_table, W1t, b1t, g_opb_t, (b - 3616) * 256 + tid);
}

// ===========================================================================
// X prep (merged tern/bin): gg < tern_cnt -> ternary row gg of Xt (width 768);
// else binary row (gg - tern_cnt) of Xb (width 512). Global row = gg.
// ===========================================================================
template <bool LEAF>
__global__ void prep_kernel(const int* __restrict__ lvl_idx, int phases, int tern_cnt,
                            const int* __restrict__ op_ids,
                            const int* __restrict__ lc, const int* __restrict__ rc,
                            const int* __restrict__ tc,
                            const int* __restrict__ comp_ids,
                            const float* __restrict__ comp_table) {
    int gg = blockIdx.x;
    bool tern = gg < tern_cnt;
    __shared__ int sids[3];
    int d = threadIdx.x;
    if (d == 0) {
        int pos = (gg & 4095) * phases + (gg >> 12);
        int node = lvl_idx[pos];
        int l = lc[node], r = rc[node];
        sids[0] = LEAF ? comp_ids[l] : l;
        sids[1] = LEAF ? comp_ids[r] : r;
        if (tern) { int t = tc[node]; sids[2] = LEAF ? comp_ids[t] : t; }
        g_nodes_l[gg] = node;
        g_op_l[gg] = op_ids[node];
    }
    __syncthreads();
    const float* src = LEAF ? comp_table : g_nodes;
    float lev = src[(size_t)sids[0] * D + d];
    float rev = src[(size_t)sids[1] * D + d];
    if (tern) {
        float tev = src[(size_t)sids[2] * D + d];
        __half* row = g_Xt_img + (size_t)gg * 768;
        row[d]       = __float2half_rn(lev);
        row[256 + d] = __float2half_rn(rev);
        row[512 + d] = __float2half_rn(tev);
        g_R[(size_t)gg * D + d] = (lev + rev + tev) * (1.0f / 3.0f);
    } else {
        __half* row = g_Xb_img + (size_t)(gg - tern_cnt) * 512;
        row[d]       = __float2half_rn(lev);
        row[256 + d] = __float2half_rn(rev);
        g_R[(size_t)gg * D + d] = lev + rev;
    }
}

// ===========================================================================
// HMMA GEMM fp16, 256 threads, double-buffered, single K pass.
// A stride = KC*64; B stride = KC*64; NC = KC chunks of 64.
// MODE 0: 128x128 tile, segment by blockIdx.x<nblk0 (tern/bin), opbias+gelu -> H (fp16).
// MODE 1: 64x256 tile, segment by row, bias+residual+LN -> scatter g_nodes.
// MODE 2: like 1 but dense out[row].
// ===========================================================================
template <int MODE>
__global__ void __launch_bounds__(256, 2)
mma_kernel(const __nv_half* __restrict__ A0, const __nv_half* __restrict__ B0,
           const float* __restrict__ bias0, int KC0, int nblk0,
           const __nv_half* __restrict__ A1, const __nv_half* __restrict__ B1,
           const float* __restrict__ bias1, int KC1,
           __half* __restrict__ Himg, const float* __restrict__ Rres,
           const float* __restrict__ gamma, const float* __restrict__ beta,
           float* __restrict__ outp) {
    constexpr int TM = (MODE == 0) ? 128 : 64;
    constexpr int TN = (MODE == 0) ? 128 : 256;
    constexpr int CHUNKE = (TM + TN) * LDS;     // fp16 elems per buffer
    constexpr int WM = TM / 32;

    extern __shared__ char smem[];
    const uint32_t sbase = smem_u32(smem);
    const int tid = threadIdx.x, wid = tid >> 5, lane = tid & 31;
    const int warp_m = wid & (WM - 1), warp_n = wid / WM;
    const int wm0 = warp_m * 32, wn0 = warp_n * 64;
    const int bx = blockIdx.x;
    const int cb0 = (MODE == 0) ? blockIdx.y * 128 : 0;

    int KC, grow0, arow0;
    const __half *Aimg, *Bimg;
    const float* bvec;
    if (MODE == 0) {
        if (bx < nblk0) { KC = KC0; Aimg = A0; Bimg = B0; bvec = bias0; arow0 = bx * 128; grow0 = arow0; }
        else { KC = KC1; Aimg = A1; Bimg = B1; bvec = bias1;
               arow0 = (bx - nblk0) * 128; grow0 = nblk0 * 128 + arow0; }
    } else {
        grow0 = bx * 64; arow0 = grow0; Aimg = A0;
        if (bx < nblk0) { KC = KC0; Bimg = B0; bvec = bias0; }
        else            { KC = KC1; Bimg = B1; bvec = bias1; }
    }
    const int stride = KC * 64;                  // both images are [rows][K]
    const __half* Bblk = Bimg + (size_t)cb0 * stride;
    const int NC = KC;

    float acc[2][8][4];
    #pragma unroll
    for (int mt = 0; mt < 2; mt++)
        #pragma unroll
        for (int nt = 0; nt < 8; nt++)
            #pragma unroll
            for (int q = 0; q < 4; q++) acc[mt][nt][q] = 0.0f;

    auto load_chunk = [&](int c, int b) {
        const int base = b * CHUNKE;
        const __half* Ab = Aimg + (size_t)arow0 * stride + c * 64;
        #pragma unroll
        for (int v = tid; v < TM * 8; v += 256) {
            int r = v >> 3, s = v & 7;
            cp_async16(sbase + (base + r * LDS + s * 8) * 2, Ab + (size_t)r * stride + s * 8);
        }
        const __half* Bb = Bblk + c * 64;
        #pragma unroll
        for (int v = tid; v < TN * 8; v += 256) {
            int r = v >> 3, s = v & 7;
            cp_async16(sbase + (base + TM * LDS + r * LDS + s * 8) * 2, Bb + (size_t)r * stride + s * 8);
        }
        cp_commit();
    };

    load_chunk(0, 0);
    for (int c = 0; c < NC; c++) {
        const int b = c & 1;
        if (c + 1 < NC) {
            load_chunk(c + 1, (c + 1) & 1);
            asm volatile("cp.async.wait_group 1;");
        } else {
            asm volatile("cp.async.wait_group 0;");
        }
        __syncthreads();

        const uint32_t aBase = sbase + (b * CHUNKE) * 2;
        const uint32_t bBase = aBase + TM * LDS * 2;
        #pragma unroll
        for (int ks = 0; ks < 4; ks++) {
            uint32_t afr[2][4];
            #pragma unroll
            for (int mt = 0; mt < 2; mt++) {
                uint32_t ad = aBase +
                    ((wm0 + mt * 16 + (lane & 15)) * LDS + ks * 16 + (lane >> 4) * 8) * 2;
                ldsm_x4(afr[mt], ad);
            }
            uint32_t bfr[4][4];
            #pragma unroll
            for (int ntp = 0; ntp < 4; ntp++) {
                int n = wn0 + ntp * 16 + (lane & 7) + ((lane >> 4) << 3);
                int koff = ks * 16 + ((lane >> 3) & 1) * 8;
                ldsm_x4(bfr[ntp], bBase + (n * LDS + koff) * 2);
            }
            #pragma unroll
            for (int mt = 0; mt < 2; mt++)
                #pragma unroll
                for (int ntp = 0; ntp < 4; ntp++) {
                    mma_f16(acc[mt][ntp * 2 + 0], afr[mt], bfr[ntp][0], bfr[ntp][1]);
                    mma_f16(acc[mt][ntp * 2 + 1], afr[mt], bfr[ntp][2], bfr[ntp][3]);
                }
        }
        __syncthreads();
    }

    // ---- epilogue --------------------------------------------------------
    if (MODE == 0) {
        uint32_t* H32 = (uint32_t*)Himg;
        #pragma unroll
        for (int mt = 0; mt < 2; mt++) {
            #pragma unroll
            for (int nt = 0; nt < 8; nt++) {
                int rl = wm0 + mt * 16 + (lane >> 2);
                int j  = cb0 + wn0 + (nt >> 1) * 16 + (nt & 1) * 8 + (lane & 3) * 2;
                #pragma unroll
                for (int hrow = 0; hrow < 2; hrow++) {
                    int grow = grow0 + rl + hrow * 8;
                    int op = g_op_l[grow];
                    float bj0 = __ldg(&bvec[op * 512 + j]);
                    float bj1 = __ldg(&bvec[op * 512 + j + 1]);
                    float h0 = gelu_exact(acc[mt][nt][hrow * 2 + 0] + bj0);
                    float h1 = gelu_exact(acc[mt][nt][hrow * 2 + 1] + bj1);
                    __half hh0 = __float2half_rn(h0);
                    __half hh1 = __float2half_rn(h1);
                    uint32_t hw = (uint32_t)__half_as_ushort(hh1) << 16 | __half_as_ushort(hh0);
                    H32[(size_t)grow * 256 + (j >> 1)] = hw;   // 512 fp16 / 2 per row
                }
            }
        }
    } else {
        float* sy = (float*)smem;                        // [64][257], buffers dead
        #pragma unroll
        for (int mt = 0; mt < 2; mt++) {
            #pragma unroll
            for (int nt = 0; nt < 8; nt++) {
                int rl  = wm0 + mt * 16 + (lane >> 2);
                int col = wn0 + (nt >> 1) * 16 + (nt & 1) * 8 + (lane & 3) * 2;
                float b0 = __ldg(&bvec[col]);
                float b1 = __ldg(&bvec[col + 1]);
                #pragma unroll
                for (int hrow = 0; hrow < 2; hrow++) {
                    int r = rl + hrow * 8;
                    int grow = grow0 + r;
                    float r0 = __ldg(&Rres[(size_t)grow * D + col]);
                    float r1 = __ldg(&Rres[(size_t)grow * D + col + 1]);
                    sy[r * 257 + col]     = acc[mt][nt][hrow * 2 + 0] + b0 + r0;
                    sy[r * 257 + col + 1] = acc[mt][nt][hrow * 2 + 1] + b1 + r1;
                }
            }
        }
        __syncthreads();
        #pragma unroll
        for (int rr = 0; rr < 8; rr++) {
            int rn = wid * 8 + rr;
            int grow = grow0 + rn;
            float vals[8];
            float s = 0.0f, s2 = 0.0f;
            #pragma unroll
            for (int k = 0; k < 8; k++) {
                float v = sy[rn * 257 + lane + k * 32];
                vals[k] = v; s += v; s2 = fmaf(v, v, s2);
            }
            #pragma unroll
            for (int off = 16; off > 0; off >>= 1) {
                s  += __shfl_xor_sync(0xFFFFFFFF, s, off);
                s2 += __shfl_xor_sync(0xFFFFFFFF, s2, off);
            }
            float mu  = s * (1.0f / 256.0f);
            float var = s2 * (1.0f / 256.0f) - mu * mu;
            float inv = rsqrtf(var + 1e-5f);
            float* dst = (MODE == 1) ? outp + (size_t)g_nodes_l[grow] * D
                                     : outp + (size_t)grow * D;
            #pragma unroll
            for (int k = 0; k < 8; k++) {
                int d = lane + k * 32;
                dst[d] = (vals[k] - mu) * inv * __ldg(&gamma[d]) + __ldg(&beta[d]);
            }
        }
    }
}

// ===========================================================================
extern "C" void kernel_launch(void* const* d_in, const int* in_sizes, int n_in,
                              void* d_out, int out_size) {
    const int*   comp_ids   = (const int*)d_in[0];
    const int*   op_ids     = (const int*)d_in[1];
    const int*   lc         = (const int*)d_in[2];
    const int*   rc         = (const int*)d_in[3];
    const int*   tc         = (const int*)d_in[4];
    const int*   lvl2       = (const int*)d_in[5];
    const int*   lvl1       = (const int*)d_in[6];
    const int*   lvl0       = (const int*)d_in[7];
    const float* comp_table = (const float*)d_in[8];
    const float* op_table   = (const float*)d_in[9];
    const float* W1b        = (const float*)d_in[10];
    const float* b1b        = (const float*)d_in[11];
    const float* W2b        = (const float*)d_in[12];
    const float* b2b        = (const float*)d_in[13];
    const float* W1t        = (const float*)d_in[14];
    const float* b1t        = (const float*)d_in[15];
    const float* W2t        = (const float*)d_in[16];
    const float* b2t        = (const float*)d_in[17];
    const float* gamma      = (const float*)d_in[18];
    const float* beta       = (const float*)d_in[19];
    float* out = (float*)d_out;

    float* p_gnodes;  cudaGetSymbolAddress((void**)&p_gnodes, g_nodes);
    float* p_R;       cudaGetSymbolAddress((void**)&p_R, g_R);
    float* p_opb_b;   cudaGetSymbolAddress((void**)&p_opb_b, g_opb_b);
    float* p_opb_t;   cudaGetSymbolAddress((void**)&p_opb_t, g_opb_t);
    __half *p_Xt, *p_Xb, *p_H, *p_W1b, *p_W1t, *p_W2b, *p_W2t;
    cudaGetSymbolAddress((void**)&p_Xt,  g_Xt_img);
    cudaGetSymbolAddress((void**)&p_Xb,  g_Xb_img);
    cudaGetSymbolAddress((void**)&p_H,   g_H_img);
    cudaGetSymbolAddress((void**)&p_W1b, g_W1b_img);
    cudaGetSymbolAddress((void**)&p_W1t, g_W1t_img);
    cudaGetSymbolAddress((void**)&p_W2b, g_W2b_img);
    cudaGetSymbolAddress((void**)&p_W2t, g_W2t_img);

    const int SMEM0 = 2 * (128 + 128) * LDS * 2;   // 73,728
    const int SMEM1 = 2 * (64 + 256) * LDS * 2;    // 92,160
    cudaFuncSetAttribute(mma_kernel<0>, cudaFuncAttributeMaxDynamicSharedMemorySize, SMEM0);
    cudaFuncSetAttribute(mma_kernel<1>, cudaFuncAttributeMaxDynamicSharedMemorySize, SMEM1);
    cudaFuncSetAttribute(mma_kernel<2>, cudaFuncAttributeMaxDynamicSharedMemorySize, SMEM1);

    // 0) all setup in one launch
    setup_kernel<<<3648, 256>>>(W1b, b1b, W2b, W1t, b1t, W2t, op_table);

    // 1) lvl2 (tern rows 0..4095, bin rows 4096..16383), leaf children
    prep_kernel<true><<<16384, 256>>>(lvl2, 4, 4096, op_ids, lc, rc, tc, comp_ids, comp_table);
    mma_kernel<0><<<dim3(128, 4), 256, SMEM0>>>(
        p_Xt, p_W1t, p_opb_t, 12, 32,
        p_Xb, p_W1b, p_opb_b, 8,
        p_H, nullptr, gamma, beta, nullptr);
    mma_kernel<1><<<256, 256, SMEM1>>>(
        p_H, p_W2t, b2t, 8, 64,
        nullptr, p_W2b, b2b, 8,
        nullptr, p_R, gamma, beta, p_gnodes);

    // 2) lvl1 (all binary)
    prep_kernel<false><<<8192, 256>>>(lvl1, 2, 0, op_ids, lc, rc, tc, comp_ids, comp_table);
    mma_kernel<0><<<dim3(64, 4), 256, SMEM0>>>(
        p_Xb, p_W1b, p_opb_b, 8, 0,
        p_Xb, p_W1b, p_opb_b, 8,
        p_H, nullptr, gamma, beta, nullptr);
    mma_kernel<1><<<128, 256, SMEM1>>>(
        p_H, p_W2b, b2b, 8, 0,
        nullptr, p_W2b, b2b, 8,
        nullptr, p_R, gamma, beta, p_gnodes);

    // 3) lvl0 (all binary) -> dense out
    prep_kernel<false><<<4096, 256>>>(lvl0, 1, 0, op_ids, lc, rc, tc, comp_ids, comp_table);
    mma_kernel<0><<<dim3(32, 4), 256, SMEM0>>>(
        p_Xb, p_W1b, p_opb_b, 8, 0,
        p_Xb, p_W1b, p_opb_b, 8,
        p_H, nullptr, gamma, beta, nullptr);
    mma_kernel<2><<<64, 256, SMEM1>>>(
        p_H, p_W2b, b2b, 8, 0,
        nullptr, p_W2b, b2b, 8,
        nullptr, p_R, gamma, beta, out);

    (void)n_in; (void)out_size;
}

// round 14
// speedup vs baseline: 2.2577x; 1.0160x over previous
#include <cuda_runtime.h>
#include <cuda_fp16.h>
#include <cstdint>
#include <math.h>

#define D 256
#define LDS 72   // smem row stride in fp16 elems (64 data + 8 pad)

// ===========================================================================
// Static device scratch (unified global row space per level: tern rows first)
// ===========================================================================
__device__ float g_nodes[65536 * D];
__device__ __half g_Xt_img[4096  * 768];       // ternary X, fp16
__device__ __half g_Xb_img[12288 * 512];       // binary  X, fp16
__device__ __half g_H_img [16384 * 512];       // H, fp16, global rows
__device__ float g_R[16384 * D];
__device__ int   g_nodes_l[16384];
__device__ int   g_op_l[16384];
__device__ __half g_W1b_img[512 * 512];        // [N=512][K=512] fp16
__device__ __half g_W1t_img[512 * 768];        // [N=512][K=768] fp16
__device__ __half g_W2b_img[256 * 512];
__device__ __half g_W2t_img[256 * 512];
__device__ float g_opb_b[16 * 512];
__device__ float g_opb_t[16 * 512];

// ===========================================================================
// Helpers (sm_80-era PTX only)
// ===========================================================================
__device__ __forceinline__ uint32_t smem_u32(const void* p) {
    uint32_t a;
    asm("{ .reg .u64 t; cvta.to.shared.u64 t, %1; cvt.u32.u64 %0, t; }" : "=r"(a) : "l"(p));
    return a;
}
__device__ __forceinline__ void cp_async16(uint32_t saddr, const void* gaddr) {
    asm volatile("cp.async.cg.shared.global [%0], [%1], 16;" :: "r"(saddr), "l"(gaddr));
}
__device__ __forceinline__ void cp_commit() {
    asm volatile("cp.async.commit_group;");
}
__device__ __forceinline__ void ldsm_x4(uint32_t* r, uint32_t addr) {
    asm volatile("ldmatrix.sync.aligned.m8n8.x4.shared.b16 {%0,%1,%2,%3}, [%4];"
                 : "=r"(r[0]), "=r"(r[1]), "=r"(r[2]), "=r"(r[3]) : "r"(addr));
}
__device__ __forceinline__ void mma_f16(float* c, const uint32_t* a, uint32_t b0, uint32_t b1) {
    asm volatile("mma.sync.aligned.m16n8k16.row.col.f32.f16.f16.f32 "
                 "{%0,%1,%2,%3}, {%4,%5,%6,%7}, {%8,%9}, {%0,%1,%2,%3};"
                 : "+f"(c[0]), "+f"(c[1]), "+f"(c[2]), "+f"(c[3])
                 : "r"(a[0]), "r"(a[1]), "r"(a[2]), "r"(a[3]), "r"(b0), "r"(b1));
}
__device__ __forceinline__ float gelu_exact(float a) {
    return 0.5f * a * (1.0f + erff(a * 0.70710678118654752f));
}

// ===========================================================================
// Setup bodies: weight images [N][K] fp16 + exact op-projection tables
// ===========================================================================
__device__ __forceinline__ void wprep_body(const float* __restrict__ W,
                                           __half* __restrict__ img,
                                           int K, int N, int idx) {
    if (idx >= K * N) return;
    int k = idx / N, n = idx % N;
    img[(size_t)n * K + k] = __float2half_rn(W[idx]);
}
__device__ __forceinline__ void opproj_body(const float* __restrict__ op_table,
                                            const float* __restrict__ W1,
                                            const float* __restrict__ b1,
                                            float* __restrict__ outb, int idx) {
    int o = idx >> 9, j = idx & 511;
    float s = b1[j];
    const float* oe = op_table + o * D;
    #pragma unroll 8
    for (int k = 0; k < D; k++)
        s = fmaf(oe[k], W1[(size_t)k * 512 + j], s);
    outb[idx] = s;
}
__device__ __forceinline__ void setup_body(int b, int tid,
                             const float* __restrict__ W1b, const float* __restrict__ b1b,
                             const float* __restrict__ W2b,
                             const float* __restrict__ W1t, const float* __restrict__ b1t,
                             const float* __restrict__ W2t,
                             const float* __restrict__ op_table) {
    if (b < 1024)      wprep_body(W1b + 256 * 512, g_W1b_img, 512, 512, b * 256 + tid);
    else if (b < 2560) wprep_body(W1t + 256 * 512, g_W1t_img, 768, 512, (b - 1024) * 256 + tid);
    else if (b < 3072) wprep_body(W2b, g_W2b_img, 512, 256, (b - 2560) * 256 + tid);
    else if (b < 3584) wprep_body(W2t, g_W2t_img, 512, 256, (b - 3072) * 256 + tid);
    else if (b < 3616) opproj_body(op_table, W1b, b1b, g_opb_b, (b - 3584) * 256 + tid);
    else               opproj_body(op_table, W1t, b1t, g_opb_t, (b - 3616) * 256 + tid);
}

// ===========================================================================
// X prep body: 8 rows per block. gg < tern_cnt -> ternary row gg of Xt (768);
// else binary row (gg - tern_cnt) of Xb (512). Global row = gg.
// ===========================================================================
template <bool LEAF>
__device__ __forceinline__ void prep_body(int blk,
                            const int* __restrict__ lvl_idx, int phases, int tern_cnt,
                            const int* __restrict__ op_ids,
                            const int* __restrict__ lc, const int* __restrict__ rc,
                            const int* __restrict__ tc,
                            const int* __restrict__ comp_ids,
                            const float* __restrict__ comp_table,
                            int* sids) {   // smem int[8][3]
    int gg0 = blk * 8;
    int d = threadIdx.x;
    if (d < 8) {
        int gg = gg0 + d;
        int pos = (gg & 4095) * phases + (gg >> 12);
        int node = lvl_idx[pos];
        int l = lc[node], r = rc[node];
        sids[d * 3 + 0] = LEAF ? comp_ids[l] : l;
        sids[d * 3 + 1] = LEAF ? comp_ids[r] : r;
        if (gg < tern_cnt) { int t = tc[node]; sids[d * 3 + 2] = LEAF ? comp_ids[t] : t; }
        g_nodes_l[gg] = node;
        g_op_l[gg] = op_ids[node];
    }
    __syncthreads();
    const float* src = LEAF ? comp_table : g_nodes;
    bool tern = gg0 < tern_cnt;   // uniform per block (tern_cnt multiple of 8)
    #pragma unroll 2
    for (int rr = 0; rr < 8; rr++) {
        int gg = gg0 + rr;
        float lev = src[(size_t)sids[rr * 3 + 0] * D + d];
        float rev = src[(size_t)sids[rr * 3 + 1] * D + d];
        if (tern) {
            float tev = src[(size_t)sids[rr * 3 + 2] * D + d];
            __half* row = g_Xt_img + (size_t)gg * 768;
            row[d]       = __float2half_rn(lev);
            row[256 + d] = __float2half_rn(rev);
            row[512 + d] = __float2half_rn(tev);
            g_R[(size_t)gg * D + d] = (lev + rev + tev) * (1.0f / 3.0f);
        } else {
            __half* row = g_Xb_img + (size_t)(gg - tern_cnt) * 512;
            row[d]       = __float2half_rn(lev);
            row[256 + d] = __float2half_rn(rev);
            g_R[(size_t)gg * D + d] = lev + rev;
        }
    }
}

template <bool LEAF>
__global__ void prep_kernel(const int* __restrict__ lvl_idx, int phases, int tern_cnt,
                            const int* __restrict__ op_ids,
                            const int* __restrict__ lc, const int* __restrict__ rc,
                            const int* __restrict__ tc,
                            const int* __restrict__ comp_ids,
                            const float* __restrict__ comp_table) {
    __shared__ int sids[24];
    prep_body<LEAF>(blockIdx.x, lvl_idx, phases, tern_cnt, op_ids, lc, rc, tc,
                    comp_ids, comp_table, sids);
}

// Merged lvl2 prep (blocks 0..2047) + setup (blocks 2048..5695)
__global__ void prep2_setup_kernel(const int* __restrict__ lvl_idx,
                            const int* __restrict__ op_ids,
                            const int* __restrict__ lc, const int* __restrict__ rc,
                            const int* __restrict__ tc,
                            const int* __restrict__ comp_ids,
                            const float* __restrict__ comp_table,
                            const float* __restrict__ W1b, const float* __restrict__ b1b,
                            const float* __restrict__ W2b,
                            const float* __restrict__ W1t, const float* __restrict__ b1t,
                            const float* __restrict__ W2t,
                            const float* __restrict__ op_table) {
    __shared__ int sids[24];
    int b = blockIdx.x;
    if (b < 2048) {
        prep_body<true>(b, lvl_idx, /*phases=*/4, /*tern_cnt=*/4096, op_ids, lc, rc, tc,
                        comp_ids, comp_table, sids);
    } else {
        setup_body(b - 2048, threadIdx.x, W1b, b1b, W2b, W1t, b1t, W2t, op_table);
    }
}

// ===========================================================================
// HMMA GEMM fp16, 256 threads, single K pass.
// MODE 0: 128x128 tile, 3-buffer single-sync pipeline, opbias+gelu -> H (fp16).
// MODE 1: 64x256 tile, 2-buffer, bias+residual+LN -> scatter g_nodes.
// MODE 2: like 1 but dense out[row].
// ===========================================================================
template <int MODE>
__global__ void __launch_bounds__(256, 2)
mma_kernel(const __nv_half* __restrict__ A0, const __nv_half* __restrict__ B0,
           const float* __restrict__ bias0, int KC0, int nblk0,
           const __nv_half* __restrict__ A1, const __nv_half* __restrict__ B1,
           const float* __restrict__ bias1, int KC1,
           __half* __restrict__ Himg, const float* __restrict__ Rres,
           const float* __restrict__ gamma, const float* __restrict__ beta,
           float* __restrict__ outp) {
    constexpr int TM = (MODE == 0) ? 128 : 64;
    constexpr int TN = (MODE == 0) ? 128 : 256;
    constexpr int CHUNKE = (TM + TN) * LDS;     // fp16 elems per buffer
    constexpr int WM = TM / 32;

    extern __shared__ char smem[];
    const uint32_t sbase = smem_u32(smem);
    const int tid = threadIdx.x, wid = tid >> 5, lane = tid & 31;
    const int warp_m = wid & (WM - 1), warp_n = wid / WM;
    const int wm0 = warp_m * 32, wn0 = warp_n * 64;
    const int bx = blockIdx.x;
    const int cb0 = (MODE == 0) ? blockIdx.y * 128 : 0;

    int KC, grow0, arow0;
    const __half *Aimg, *Bimg;
    const float* bvec;
    if (MODE == 0) {
        if (bx < nblk0) { KC = KC0; Aimg = A0; Bimg = B0; bvec = bias0; arow0 = bx * 128; grow0 = arow0; }
        else { KC = KC1; Aimg = A1; Bimg = B1; bvec = bias1;
               arow0 = (bx - nblk0) * 128; grow0 = nblk0 * 128 + arow0; }
    } else {
        grow0 = bx * 64; arow0 = grow0; Aimg = A0;
        if (bx < nblk0) { KC = KC0; Bimg = B0; bvec = bias0; }
        else            { KC = KC1; Bimg = B1; bvec = bias1; }
    }
    const int stride = KC * 64;                  // both images are [rows][K]
    const __half* Bblk = Bimg + (size_t)cb0 * stride;
    const int NC = KC;

    float acc[2][8][4];
    #pragma unroll
    for (int mt = 0; mt < 2; mt++)
        #pragma unroll
        for (int nt = 0; nt < 8; nt++)
            #pragma unroll
            for (int q = 0; q < 4; q++) acc[mt][nt][q] = 0.0f;

    auto load_chunk = [&](int c, int b) {
        const int base = b * CHUNKE;
        const __half* Ab = Aimg + (size_t)arow0 * stride + c * 64;
        #pragma unroll
        for (int v = tid; v < TM * 8; v += 256) {
            int r = v >> 3, s = v & 7;
            cp_async16(sbase + (base + r * LDS + s * 8) * 2, Ab + (size_t)r * stride + s * 8);
        }
        const __half* Bb = Bblk + c * 64;
        #pragma unroll
        for (int v = tid; v < TN * 8; v += 256) {
            int r = v >> 3, s = v & 7;
            cp_async16(sbase + (base + TM * LDS + r * LDS + s * 8) * 2, Bb + (size_t)r * stride + s * 8);
        }
        cp_commit();
    };

    auto compute_chunk = [&](int b) {
        const uint32_t aBase = sbase + (b * CHUNKE) * 2;
        const uint32_t bBase = aBase + TM * LDS * 2;
        #pragma unroll
        for (int ks = 0; ks < 4; ks++) {
            uint32_t afr[2][4];
            #pragma unroll
            for (int mt = 0; mt < 2; mt++) {
                uint32_t ad = aBase +
                    ((wm0 + mt * 16 + (lane & 15)) * LDS + ks * 16 + (lane >> 4) * 8) * 2;
                ldsm_x4(afr[mt], ad);
            }
            uint32_t bfr[4][4];
            #pragma unroll
            for (int ntp = 0; ntp < 4; ntp++) {
                int n = wn0 + ntp * 16 + (lane & 7) + ((lane >> 4) << 3);
                int koff = ks * 16 + ((lane >> 3) & 1) * 8;
                ldsm_x4(bfr[ntp], bBase + (n * LDS + koff) * 2);
            }
            #pragma unroll
            for (int mt = 0; mt < 2; mt++)
                #pragma unroll
                for (int ntp = 0; ntp < 4; ntp++) {
                    mma_f16(acc[mt][ntp * 2 + 0], afr[mt], bfr[ntp][0], bfr[ntp][1]);
                    mma_f16(acc[mt][ntp * 2 + 1], afr[mt], bfr[ntp][2], bfr[ntp][3]);
                }
        }
    };

    if (MODE == 0) {
        // 3-buffer, single-sync pipeline. Load for c+2 issued AFTER the top
        // barrier of iter c, which orders it against compute of c-1 (the last
        // user of buffer (c+2)%3). Chunk c is 2-deep prefetched.
        load_chunk(0, 0);
        load_chunk(1, 1);
        for (int c = 0; c < NC; c++) {
            if (c < NC - 1) asm volatile("cp.async.wait_group 1;");
            else            asm volatile("cp.async.wait_group 0;");
            __syncthreads();
            if (c + 2 < NC) load_chunk(c + 2, (c + 2) % 3);
            compute_chunk(c % 3);
        }
        __syncthreads();
    } else {
        load_chunk(0, 0);
        for (int c = 0; c < NC; c++) {
            const int b = c & 1;
            if (c + 1 < NC) {
                load_chunk(c + 1, (c + 1) & 1);
                asm volatile("cp.async.wait_group 1;");
            } else {
                asm volatile("cp.async.wait_group 0;");
            }
            __syncthreads();
            compute_chunk(b);
            __syncthreads();
        }
    }

    // ---- epilogue --------------------------------------------------------
    if (MODE == 0) {
        uint32_t* H32 = (uint32_t*)Himg;
        #pragma unroll
        for (int mt = 0; mt < 2; mt++) {
            #pragma unroll
            for (int nt = 0; nt < 8; nt++) {
                int rl = wm0 + mt * 16 + (lane >> 2);
                int j  = cb0 + wn0 + (nt >> 1) * 16 + (nt & 1) * 8 + (lane & 3) * 2;
                #pragma unroll
                for (int hrow = 0; hrow < 2; hrow++) {
                    int grow = grow0 + rl + hrow * 8;
                    int op = g_op_l[grow];
                    float bj0 = __ldg(&bvec[op * 512 + j]);
                    float bj1 = __ldg(&bvec[op * 512 + j + 1]);
                    float h0 = gelu_exact(acc[mt][nt][hrow * 2 + 0] + bj0);
                    float h1 = gelu_exact(acc[mt][nt][hrow * 2 + 1] + bj1);
                    __half hh0 = __float2half_rn(h0);
                    __half hh1 = __float2half_rn(h1);
                    uint32_t hw = (uint32_t)__half_as_ushort(hh1) << 16 | __half_as_ushort(hh0);
                    H32[(size_t)grow * 256 + (j >> 1)] = hw;   // 512 fp16 / 2 per row
                }
            }
        }
    } else {
        float* sy = (float*)smem;                        // [64][257], buffers dead
        #pragma unroll
        for (int mt = 0; mt < 2; mt++) {
            #pragma unroll
            for (int nt = 0; nt < 8; nt++) {
                int rl  = wm0 + mt * 16 + (lane >> 2);
                int col = wn0 + (nt >> 1) * 16 + (nt & 1) * 8 + (lane & 3) * 2;
                float b0 = __ldg(&bvec[col]);
                float b1 = __ldg(&bvec[col + 1]);
                #pragma unroll
                for (int hrow = 0; hrow < 2; hrow++) {
                    int r = rl + hrow * 8;
                    int grow = grow0 + r;
                    float r0 = __ldg(&Rres[(size_t)grow * D + col]);
                    float r1 = __ldg(&Rres[(size_t)grow * D + col + 1]);
                    sy[r * 257 + col]     = acc[mt][nt][hrow * 2 + 0] + b0 + r0;
                    sy[r * 257 + col + 1] = acc[mt][nt][hrow * 2 + 1] + b1 + r1;
                }
            }
        }
        __syncthreads();
        #pragma unroll
        for (int rr = 0; rr < 8; rr++) {
            int rn = wid * 8 + rr;
            int grow = grow0 + rn;
            float vals[8];
            float s = 0.0f, s2 = 0.0f;
            #pragma unroll
            for (int k = 0; k < 8; k++) {
                float v = sy[rn * 257 + lane + k * 32];
                vals[k] = v; s += v; s2 = fmaf(v, v, s2);
            }
            #pragma unroll
            for (int off = 16; off > 0; off >>= 1) {
                s  += __shfl_xor_sync(0xFFFFFFFF, s, off);
                s2 += __shfl_xor_sync(0xFFFFFFFF, s2, off);
            }
            float mu  = s * (1.0f / 256.0f);
            float var = s2 * (1.0f / 256.0f) - mu * mu;
            float inv = rsqrtf(var + 1e-5f);
            float* dst = (MODE == 1) ? outp + (size_t)g_nodes_l[grow] * D
                                     : outp + (size_t)grow * D;
            #pragma unroll
            for (int k = 0; k < 8; k++) {
                int d = lane + k * 32;
                dst[d] = (vals[k] - mu) * inv * __ldg(&gamma[d]) + __ldg(&beta[d]);
            }
        }
    }
}

// ===========================================================================
extern "C" void kernel_launch(void* const* d_in, const int* in_sizes, int n_in,
                              void* d_out, int out_size) {
    const int*   comp_ids   = (const int*)d_in[0];
    const int*   op_ids     = (const int*)d_in[1];
    const int*   lc         = (const int*)d_in[2];
    const int*   rc         = (const int*)d_in[3];
    const int*   tc         = (const int*)d_in[4];
    const int*   lvl2       = (const int*)d_in[5];
    const int*   lvl1       = (const int*)d_in[6];
    const int*   lvl0       = (const int*)d_in[7];
    const float* comp_table = (const float*)d_in[8];
    const float* op_table   = (const float*)d_in[9];
    const float* W1b        = (const float*)d_in[10];
    const float* b1b        = (const float*)d_in[11];
    const float* W2b        = (const float*)d_in[12];
    const float* b2b        = (const float*)d_in[13];
    const float* W1t        = (const float*)d_in[14];
    const float* b1t        = (const float*)d_in[15];
    const float* W2t        = (const float*)d_in[16];
    const float* b2t        = (const float*)d_in[17];
    const float* gamma      = (const float*)d_in[18];
    const float* beta       = (const float*)d_in[19];
    float* out = (float*)d_out;

    float* p_gnodes;  cudaGetSymbolAddress((void**)&p_gnodes, g_nodes);
    float* p_R;       cudaGetSymbolAddress((void**)&p_R, g_R);
    float* p_opb_b;   cudaGetSymbolAddress((void**)&p_opb_b, g_opb_b);
    float* p_opb_t;   cudaGetSymbolAddress((void**)&p_opb_t, g_opb_t);
    __half *p_Xt, *p_Xb, *p_H, *p_W1b, *p_W1t, *p_W2b, *p_W2t;
    cudaGetSymbolAddress((void**)&p_Xt,  g_Xt_img);
    cudaGetSymbolAddress((void**)&p_Xb,  g_Xb_img);
    cudaGetSymbolAddress((void**)&p_H,   g_H_img);
    cudaGetSymbolAddress((void**)&p_W1b, g_W1b_img);
    cudaGetSymbolAddress((void**)&p_W1t, g_W1t_img);
    cudaGetSymbolAddress((void**)&p_W2b, g_W2b_img);
    cudaGetSymbolAddress((void**)&p_W2t, g_W2t_img);

    const int SMEM0 = 3 * (128 + 128) * LDS * 2;   // 110,592 (3 buffers)
    const int SMEM1 = 2 * (64 + 256) * LDS * 2;    // 92,160
    cudaFuncSetAttribute(mma_kernel<0>, cudaFuncAttributeMaxDynamicSharedMemorySize, SMEM0);
    cudaFuncSetAttribute(mma_kernel<1>, cudaFuncAttributeMaxDynamicSharedMemorySize, SMEM1);
    cudaFuncSetAttribute(mma_kernel<2>, cudaFuncAttributeMaxDynamicSharedMemorySize, SMEM1);

    // 1) lvl2 prep (2048 blocks) + all setup (3648 blocks) in ONE launch
    prep2_setup_kernel<<<5696, 256>>>(lvl2, op_ids, lc, rc, tc, comp_ids, comp_table,
                                      W1b, b1b, W2b, W1t, b1t, W2t, op_table);
    mma_kernel<0><<<dim3(128, 4), 256, SMEM0>>>(
        p_Xt, p_W1t, p_opb_t, 12, 32,
        p_Xb, p_W1b, p_opb_b, 8,
        p_H, nullptr, gamma, beta, nullptr);
    mma_kernel<1><<<256, 256, SMEM1>>>(
        p_H, p_W2t, b2t, 8, 64,
        nullptr, p_W2b, b2b, 8,
        nullptr, p_R, gamma, beta, p_gnodes);

    // 2) lvl1 (all binary)
    prep_kernel<false><<<1024, 256>>>(lvl1, 2, 0, op_ids, lc, rc, tc, comp_ids, comp_table);
    mma_kernel<0><<<dim3(64, 4), 256, SMEM0>>>(
        p_Xb, p_W1b, p_opb_b, 8, 0,
        p_Xb, p_W1b, p_opb_b, 8,
        p_H, nullptr, gamma, beta, nullptr);
    mma_kernel<1><<<128, 256, SMEM1>>>(
        p_H, p_W2b, b2b, 8, 0,
        nullptr, p_W2b, b2b, 8,
        nullptr, p_R, gamma, beta, p_gnodes);

    // 3) lvl0 (all binary) -> dense out
    prep_kernel<false><<<512, 256>>>(lvl0, 1, 0, op_ids, lc, rc, tc, comp_ids, comp_table);
    mma_kernel<0><<<dim3(32, 4), 256, SMEM0>>>(
        p_Xb, p_W1b, p_opb_b, 8, 0,
        p_Xb, p_W1b, p_opb_b, 8,
        p_H, nullptr, gamma, beta, nullptr);
    mma_kernel<2><<<64, 256, SMEM1>>>(
        p_H, p_W2b, b2b, 8, 0,
        nullptr, p_W2b, b2b, 8,
        nullptr, p_R, gamma, beta, out);

    (void)n_in; (void)out_size;
}

// round 15
// speedup vs baseline: 2.6132x; 1.1575x over previous
#include <cuda_runtime.h>
#include <cuda_fp16.h>
#include <cstdint>
#include <math.h>

#define D 256
#define LDS 72   // smem row stride in fp16 elems (64 data + 8 pad)

// ===========================================================================
// Static device scratch. Global row spaces:
//   lvl2: rows 0..16383 (tern slot3 = rows 0..4095, then bin phases 1..3)
//   lvl1: rows 0..8191  (gg1 = (p-1)*4096 + t, p in {1,2})
//   lvl0: rows 0..4095  (gg0 = t)
// ===========================================================================
__device__ __half g_Xt_img[4096  * 768];       // lvl2 ternary X
__device__ __half g_Xb_img[12288 * 512];       // lvl2 binary X
__device__ __half g_X1_img[8192  * 512];       // lvl1 X (written by lvl2 GEMM2)
__device__ __half g_X0_img[4096  * 512];       // lvl0 X (written by lvl1 GEMM2)
__device__ __half g_H_img [16384 * 512];       // H, fp16
__device__ float g_R2[16384 * D];              // lvl2 residual (from prep)
__device__ float g_child1[8192 * 512];         // lvl1 children, fp32 (residual src)
__device__ float g_child0[4096 * 512];         // lvl0 children, fp32
__device__ int   g_op2[16384];
__device__ int   g_op1[8192];
__device__ int   g_op0[4096];
__device__ __half g_W1b_img[512 * 512];
__device__ __half g_W1t_img[512 * 768];
__device__ __half g_W2b_img[256 * 512];
__device__ __half g_W2t_img[256 * 512];
__device__ float g_opb_b[16 * 512];
__device__ float g_opb_t[16 * 512];

// ===========================================================================
// Helpers (sm_80-era PTX only)
// ===========================================================================
__device__ __forceinline__ uint32_t smem_u32(const void* p) {
    uint32_t a;
    asm("{ .reg .u64 t; cvta.to.shared.u64 t, %1; cvt.u32.u64 %0, t; }" : "=r"(a) : "l"(p));
    return a;
}
__device__ __forceinline__ void cp_async16(uint32_t saddr, const void* gaddr) {
    asm volatile("cp.async.cg.shared.global [%0], [%1], 16;" :: "r"(saddr), "l"(gaddr));
}
__device__ __forceinline__ void cp_commit() {
    asm volatile("cp.async.commit_group;");
}
__device__ __forceinline__ void ldsm_x4(uint32_t* r, uint32_t addr) {
    asm volatile("ldmatrix.sync.aligned.m8n8.x4.shared.b16 {%0,%1,%2,%3}, [%4];"
                 : "=r"(r[0]), "=r"(r[1]), "=r"(r[2]), "=r"(r[3]) : "r"(addr));
}
__device__ __forceinline__ void mma_f16(float* c, const uint32_t* a, uint32_t b0, uint32_t b1) {
    asm volatile("mma.sync.aligned.m16n8k16.row.col.f32.f16.f16.f32 "
                 "{%0,%1,%2,%3}, {%4,%5,%6,%7}, {%8,%9}, {%0,%1,%2,%3};"
                 : "+f"(c[0]), "+f"(c[1]), "+f"(c[2]), "+f"(c[3])
                 : "r"(a[0]), "r"(a[1]), "r"(a[2]), "r"(a[3]), "r"(b0), "r"(b1));
}
__device__ __forceinline__ float gelu_exact(float a) {
    return 0.5f * a * (1.0f + erff(a * 0.70710678118654752f));
}

// ===========================================================================
// Setup bodies
// ===========================================================================
__device__ __forceinline__ void wprep_body(const float* __restrict__ W,
                                           __half* __restrict__ img,
                                           int K, int N, int idx) {
    if (idx >= K * N) return;
    int k = idx / N, n = idx % N;
    img[(size_t)n * K + k] = __float2half_rn(W[idx]);
}
__device__ __forceinline__ void opproj_body(const float* __restrict__ op_table,
                                            const float* __restrict__ W1,
                                            const float* __restrict__ b1,
                                            float* __restrict__ outb, int idx) {
    int o = idx >> 9, j = idx & 511;
    float s = b1[j];
    const float* oe = op_table + o * D;
    #pragma unroll 8
    for (int k = 0; k < D; k++)
        s = fmaf(oe[k], W1[(size_t)k * 512 + j], s);
    outb[idx] = s;
}
__device__ __forceinline__ void setup_body(int b, int tid,
                             const float* __restrict__ W1b, const float* __restrict__ b1b,
                             const float* __restrict__ W2b,
                             const float* __restrict__ W1t, const float* __restrict__ b1t,
                             const float* __restrict__ W2t,
                             const float* __restrict__ op_table,
                             const int* __restrict__ op_ids,
                             const int* __restrict__ lvl1_idx,
                             const int* __restrict__ lvl0_idx) {
    if (b < 1024)      wprep_body(W1b + 256 * 512, g_W1b_img, 512, 512, b * 256 + tid);
    else if (b < 2560) wprep_body(W1t + 256 * 512, g_W1t_img, 768, 512, (b - 1024) * 256 + tid);
    else if (b < 3072) wprep_body(W2b, g_W2b_img, 512, 256, (b - 2560) * 256 + tid);
    else if (b < 3584) wprep_body(W2t, g_W2t_img, 512, 256, (b - 3072) * 256 + tid);
    else if (b < 3616) opproj_body(op_table, W1b, b1b, g_opb_b, (b - 3584) * 256 + tid);
    else if (b < 3648) opproj_body(op_table, W1t, b1t, g_opb_t, (b - 3616) * 256 + tid);
    else if (b < 3680) {                       // g_op1: 8192 entries
        int i = (b - 3648) * 256 + tid;
        g_op1[i] = op_ids[lvl1_idx[(i & 4095) * 2 + (i >> 12)]];
    } else {                                   // g_op0: 4096 entries
        int i = (b - 3680) * 256 + tid;
        g_op0[i] = op_ids[lvl0_idx[i]];
    }
}

// ===========================================================================
// lvl2 X prep body: 8 rows per block, leaves from comp_table.
// ===========================================================================
__device__ __forceinline__ void prep_body(int blk,
                            const int* __restrict__ lvl_idx,
                            const int* __restrict__ op_ids,
                            const int* __restrict__ lc, const int* __restrict__ rc,
                            const int* __restrict__ tc,
                            const int* __restrict__ comp_ids,
                            const float* __restrict__ comp_table,
                            int* sids) {   // smem int[8][3]
    int gg0 = blk * 8;
    int d = threadIdx.x;
    if (d < 8) {
        int gg = gg0 + d;
        int pos = (gg & 4095) * 4 + (gg >> 12);
        int node = lvl_idx[pos];
        int l = lc[node], r = rc[node];
        sids[d * 3 + 0] = comp_ids[l];
        sids[d * 3 + 1] = comp_ids[r];
        if (gg < 4096) { int t = tc[node]; sids[d * 3 + 2] = comp_ids[t]; }
        g_op2[gg] = op_ids[node];
    }
    __syncthreads();
    bool tern = gg0 < 4096;
    #pragma unroll 2
    for (int rr = 0; rr < 8; rr++) {
        int gg = gg0 + rr;
        float lev = comp_table[(size_t)sids[rr * 3 + 0] * D + d];
        float rev = comp_table[(size_t)sids[rr * 3 + 1] * D + d];
        if (tern) {
            float tev = comp_table[(size_t)sids[rr * 3 + 2] * D + d];
            __half* row = g_Xt_img + (size_t)gg * 768;
            row[d]       = __float2half_rn(lev);
            row[256 + d] = __float2half_rn(rev);
            row[512 + d] = __float2half_rn(tev);
            g_R2[(size_t)gg * D + d] = (lev + rev + tev) * (1.0f / 3.0f);
        } else {
            __half* row = g_Xb_img + (size_t)(gg - 4096) * 512;
            row[d]       = __float2half_rn(lev);
            row[256 + d] = __float2half_rn(rev);
            g_R2[(size_t)gg * D + d] = lev + rev;
        }
    }
}

// Merged lvl2 prep (blocks 0..2047) + setup (blocks 2048..5743)
__global__ void prep2_setup_kernel(const int* __restrict__ lvl2_idx,
                            const int* __restrict__ op_ids,
                            const int* __restrict__ lc, const int* __restrict__ rc,
                            const int* __restrict__ tc,
                            const int* __restrict__ comp_ids,
                            const float* __restrict__ comp_table,
                            const float* __restrict__ W1b, const float* __restrict__ b1b,
                            const float* __restrict__ W2b,
                            const float* __restrict__ W1t, const float* __restrict__ b1t,
                            const float* __restrict__ W2t,
                            const float* __restrict__ op_table,
                            const int* __restrict__ lvl1_idx,
                            const int* __restrict__ lvl0_idx) {
    __shared__ int sids[24];
    int b = blockIdx.x;
    if (b < 2048) {
        prep_body(b, lvl2_idx, op_ids, lc, rc, tc, comp_ids, comp_table, sids);
    } else {
        setup_body(b - 2048, threadIdx.x, W1b, b1b, W2b, W1t, b1t, W2t, op_table,
                   op_ids, lvl1_idx, lvl0_idx);
    }
}

// ===========================================================================
// HMMA GEMM fp16, 256 threads, single K pass.
// MODE 0: GEMM1, 128x128 tile, 3-buffer pipeline, opbias+gelu -> H (fp16).
// MODE 1: GEMM2 lvl2, 64x256. Residual from Rres. Dest: X1 + child1,
//         mapping: phase=g>>12, t=g&4095, p=(2+phase)>>1, cs=(2+phase)&1,
//         destrow=(p-1)*4096+t.
// MODE 2: GEMM2 lvl1. Residual = child_in[g*512+col]+child_in[g*512+256+col].
//         Dest: X0 + child0, destrow = g&4095, cs = g>>12.
// MODE 3: GEMM2 lvl0. Residual from child_in. Dest: out[g*256+...].
// ===========================================================================
template <int MODE>
__global__ void __launch_bounds__(256, 2)
mma_kernel(const __nv_half* __restrict__ A0, const __nv_half* __restrict__ B0,
           const float* __restrict__ bias0, int KC0, int nblk0,
           const __nv_half* __restrict__ A1, const __nv_half* __restrict__ B1,
           const float* __restrict__ bias1, int KC1,
           const int* __restrict__ oparr,
           __half* __restrict__ Himg,
           const float* __restrict__ Rres, const float* __restrict__ child_in,
           __half* __restrict__ Xnext, float* __restrict__ child_out,
           const float* __restrict__ gamma, const float* __restrict__ beta,
           float* __restrict__ outp) {
    constexpr int TM = (MODE == 0) ? 128 : 64;
    constexpr int TN = (MODE == 0) ? 128 : 256;
    constexpr int CHUNKE = (TM + TN) * LDS;     // fp16 elems per buffer
    constexpr int WM = TM / 32;

    extern __shared__ char smem[];
    const uint32_t sbase = smem_u32(smem);
    const int tid = threadIdx.x, wid = tid >> 5, lane = tid & 31;
    const int warp_m = wid & (WM - 1), warp_n = wid / WM;
    const int wm0 = warp_m * 32, wn0 = warp_n * 64;
    const int bx = blockIdx.x;
    const int cb0 = (MODE == 0) ? blockIdx.y * 128 : 0;

    int KC, grow0, arow0;
    const __half *Aimg, *Bimg;
    const float* bvec;
    if (MODE == 0) {
        if (bx < nblk0) { KC = KC0; Aimg = A0; Bimg = B0; bvec = bias0; arow0 = bx * 128; grow0 = arow0; }
        else { KC = KC1; Aimg = A1; Bimg = B1; bvec = bias1;
               arow0 = (bx - nblk0) * 128; grow0 = nblk0 * 128 + arow0; }
    } else {
        grow0 = bx * 64; arow0 = grow0; Aimg = A0;
        if (bx < nblk0) { KC = KC0; Bimg = B0; bvec = bias0; }
        else            { KC = KC1; Bimg = B1; bvec = bias1; }
    }
    const int stride = KC * 64;                  // both images are [rows][K]
    const __half* Bblk = Bimg + (size_t)cb0 * stride;
    const int NC = KC;

    float acc[2][8][4];
    #pragma unroll
    for (int mt = 0; mt < 2; mt++)
        #pragma unroll
        for (int nt = 0; nt < 8; nt++)
            #pragma unroll
            for (int q = 0; q < 4; q++) acc[mt][nt][q] = 0.0f;

    auto load_chunk = [&](int c, int b) {
        const int base = b * CHUNKE;
        const __half* Ab = Aimg + (size_t)arow0 * stride + c * 64;
        #pragma unroll
        for (int v = tid; v < TM * 8; v += 256) {
            int r = v >> 3, s = v & 7;
            cp_async16(sbase + (base + r * LDS + s * 8) * 2, Ab + (size_t)r * stride + s * 8);
        }
        const __half* Bb = Bblk + c * 64;
        #pragma unroll
        for (int v = tid; v < TN * 8; v += 256) {
            int r = v >> 3, s = v & 7;
            cp_async16(sbase + (base + TM * LDS + r * LDS + s * 8) * 2, Bb + (size_t)r * stride + s * 8);
        }
        cp_commit();
    };

    auto compute_chunk = [&](int b) {
        const uint32_t aBase = sbase + (b * CHUNKE) * 2;
        const uint32_t bBase = aBase + TM * LDS * 2;
        #pragma unroll
        for (int ks = 0; ks < 4; ks++) {
            uint32_t afr[2][4];
            #pragma unroll
            for (int mt = 0; mt < 2; mt++) {
                uint32_t ad = aBase +
                    ((wm0 + mt * 16 + (lane & 15)) * LDS + ks * 16 + (lane >> 4) * 8) * 2;
                ldsm_x4(afr[mt], ad);
            }
            uint32_t bfr[4][4];
            #pragma unroll
            for (int ntp = 0; ntp < 4; ntp++) {
                int n = wn0 + ntp * 16 + (lane & 7) + ((lane >> 4) << 3);
                int koff = ks * 16 + ((lane >> 3) & 1) * 8;
                ldsm_x4(bfr[ntp], bBase + (n * LDS + koff) * 2);
            }
            #pragma unroll
            for (int mt = 0; mt < 2; mt++)
                #pragma unroll
                for (int ntp = 0; ntp < 4; ntp++) {
                    mma_f16(acc[mt][ntp * 2 + 0], afr[mt], bfr[ntp][0], bfr[ntp][1]);
                    mma_f16(acc[mt][ntp * 2 + 1], afr[mt], bfr[ntp][2], bfr[ntp][3]);
                }
        }
    };

    if (MODE == 0) {
        // 3-buffer, single-sync pipeline (see R13 notes).
        load_chunk(0, 0);
        load_chunk(1, 1);
        for (int c = 0; c < NC; c++) {
            if (c < NC - 1) asm volatile("cp.async.wait_group 1;");
            else            asm volatile("cp.async.wait_group 0;");
            __syncthreads();
            if (c + 2 < NC) load_chunk(c + 2, (c + 2) % 3);
            compute_chunk(c % 3);
        }
        __syncthreads();
    } else {
        load_chunk(0, 0);
        for (int c = 0; c < NC; c++) {
            const int b = c & 1;
            if (c + 1 < NC) {
                load_chunk(c + 1, (c + 1) & 1);
                asm volatile("cp.async.wait_group 1;");
            } else {
                asm volatile("cp.async.wait_group 0;");
            }
            __syncthreads();
            compute_chunk(b);
            __syncthreads();
        }
    }

    // ---- epilogue --------------------------------------------------------
    if (MODE == 0) {
        uint32_t* H32 = (uint32_t*)Himg;
        #pragma unroll
        for (int mt = 0; mt < 2; mt++) {
            #pragma unroll
            for (int nt = 0; nt < 8; nt++) {
                int rl = wm0 + mt * 16 + (lane >> 2);
                int j  = cb0 + wn0 + (nt >> 1) * 16 + (nt & 1) * 8 + (lane & 3) * 2;
                #pragma unroll
                for (int hrow = 0; hrow < 2; hrow++) {
                    int grow = grow0 + rl + hrow * 8;
                    int op = __ldg(&oparr[grow]);
                    float bj0 = __ldg(&bvec[op * 512 + j]);
                    float bj1 = __ldg(&bvec[op * 512 + j + 1]);
                    float h0 = gelu_exact(acc[mt][nt][hrow * 2 + 0] + bj0);
                    float h1 = gelu_exact(acc[mt][nt][hrow * 2 + 1] + bj1);
                    __half hh0 = __float2half_rn(h0);
                    __half hh1 = __float2half_rn(h1);
                    uint32_t hw = (uint32_t)__half_as_ushort(hh1) << 16 | __half_as_ushort(hh0);
                    H32[(size_t)grow * 256 + (j >> 1)] = hw;
                }
            }
        }
    } else {
        float* sy = (float*)smem;                        // [64][257], buffers dead
        #pragma unroll
        for (int mt = 0; mt < 2; mt++) {
            #pragma unroll
            for (int nt = 0; nt < 8; nt++) {
                int rl  = wm0 + mt * 16 + (lane >> 2);
                int col = wn0 + (nt >> 1) * 16 + (nt & 1) * 8 + (lane & 3) * 2;
                float b0 = __ldg(&bvec[col]);
                float b1 = __ldg(&bvec[col + 1]);
                #pragma unroll
                for (int hrow = 0; hrow < 2; hrow++) {
                    int r = rl + hrow * 8;
                    int grow = grow0 + r;
                    float r0, r1;
                    if (MODE == 1) {
                        r0 = __ldg(&Rres[(size_t)grow * D + col]);
                        r1 = __ldg(&Rres[(size_t)grow * D + col + 1]);
                    } else {
                        r0 = __ldg(&child_in[(size_t)grow * 512 + col]) +
                             __ldg(&child_in[(size_t)grow * 512 + 256 + col]);
                        r1 = __ldg(&child_in[(size_t)grow * 512 + col + 1]) +
                             __ldg(&child_in[(size_t)grow * 512 + 256 + col + 1]);
                    }
                    sy[r * 257 + col]     = acc[mt][nt][hrow * 2 + 0] + b0 + r0;
                    sy[r * 257 + col + 1] = acc[mt][nt][hrow * 2 + 1] + b1 + r1;
                }
            }
        }
        __syncthreads();
        #pragma unroll
        for (int rr = 0; rr < 8; rr++) {
            int rn = wid * 8 + rr;
            int grow = grow0 + rn;
            float vals[8];
            float s = 0.0f, s2 = 0.0f;
            #pragma unroll
            for (int k = 0; k < 8; k++) {
                float v = sy[rn * 257 + lane + k * 32];
                vals[k] = v; s += v; s2 = fmaf(v, v, s2);
            }
            #pragma unroll
            for (int off = 16; off > 0; off >>= 1) {
                s  += __shfl_xor_sync(0xFFFFFFFF, s, off);
                s2 += __shfl_xor_sync(0xFFFFFFFF, s2, off);
            }
            float mu  = s * (1.0f / 256.0f);
            float var = s2 * (1.0f / 256.0f) - mu * mu;
            float inv = rsqrtf(var + 1e-5f);
            // destination mapping
            int t = grow & 4095, phase = grow >> 12;
            size_t dbase;
            if (MODE == 1) {
                int p  = (2 + phase) >> 1;       // parent slot 1 or 2
                int cs = (2 + phase) & 1;        // 0=left, 1=right
                dbase = ((size_t)((p - 1) * 4096 + t)) * 512 + cs * 256;
            } else if (MODE == 2) {
                dbase = (size_t)t * 512 + phase * 256;   // phase = p-1
            } else {
                dbase = (size_t)grow * 256;
            }
            #pragma unroll
            for (int k = 0; k < 8; k++) {
                int d = lane + k * 32;
                float y = (vals[k] - mu) * inv * __ldg(&gamma[d]) + __ldg(&beta[d]);
                if (MODE == 3) {
                    outp[dbase + d] = y;
                } else {
                    Xnext[dbase + d] = __float2half_rn(y);
                    child_out[dbase + d] = y;
                }
            }
        }
    }
}

// ===========================================================================
extern "C" void kernel_launch(void* const* d_in, const int* in_sizes, int n_in,
                              void* d_out, int out_size) {
    const int*   comp_ids   = (const int*)d_in[0];
    const int*   op_ids     = (const int*)d_in[1];
    const int*   lc         = (const int*)d_in[2];
    const int*   rc         = (const int*)d_in[3];
    const int*   tc         = (const int*)d_in[4];
    const int*   lvl2       = (const int*)d_in[5];
    const int*   lvl1       = (const int*)d_in[6];
    const int*   lvl0       = (const int*)d_in[7];
    const float* comp_table = (const float*)d_in[8];
    const float* op_table   = (const float*)d_in[9];
    const float* W1b        = (const float*)d_in[10];
    const float* b1b        = (const float*)d_in[11];
    const float* W2b        = (const float*)d_in[12];
    const float* b2b        = (const float*)d_in[13];
    const float* W1t        = (const float*)d_in[14];
    const float* b1t        = (const float*)d_in[15];
    const float* W2t        = (const float*)d_in[16];
    const float* b2t        = (const float*)d_in[17];
    const float* gamma      = (const float*)d_in[18];
    const float* beta       = (const float*)d_in[19];
    float* out = (float*)d_out;

    float* p_R2;      cudaGetSymbolAddress((void**)&p_R2, g_R2);
    float* p_c1;      cudaGetSymbolAddress((void**)&p_c1, g_child1);
    float* p_c0;      cudaGetSymbolAddress((void**)&p_c0, g_child0);
    float* p_opb_b;   cudaGetSymbolAddress((void**)&p_opb_b, g_opb_b);
    float* p_opb_t;   cudaGetSymbolAddress((void**)&p_opb_t, g_opb_t);
    int *p_op2, *p_op1, *p_op0;
    cudaGetSymbolAddress((void**)&p_op2, g_op2);
    cudaGetSymbolAddress((void**)&p_op1, g_op1);
    cudaGetSymbolAddress((void**)&p_op0, g_op0);
    __half *p_Xt, *p_Xb, *p_X1, *p_X0, *p_H, *p_W1b, *p_W1t, *p_W2b, *p_W2t;
    cudaGetSymbolAddress((void**)&p_Xt,  g_Xt_img);
    cudaGetSymbolAddress((void**)&p_Xb,  g_Xb_img);
    cudaGetSymbolAddress((void**)&p_X1,  g_X1_img);
    cudaGetSymbolAddress((void**)&p_X0,  g_X0_img);
    cudaGetSymbolAddress((void**)&p_H,   g_H_img);
    cudaGetSymbolAddress((void**)&p_W1b, g_W1b_img);
    cudaGetSymbolAddress((void**)&p_W1t, g_W1t_img);
    cudaGetSymbolAddress((void**)&p_W2b, g_W2b_img);
    cudaGetSymbolAddress((void**)&p_W2t, g_W2t_img);

    const int SMEM0 = 3 * (128 + 128) * LDS * 2;   // 110,592 (3 buffers)
    const int SMEM1 = 2 * (64 + 256) * LDS * 2;    // 92,160
    cudaFuncSetAttribute(mma_kernel<0>, cudaFuncAttributeMaxDynamicSharedMemorySize, SMEM0);
    cudaFuncSetAttribute(mma_kernel<1>, cudaFuncAttributeMaxDynamicSharedMemorySize, SMEM1);
    cudaFuncSetAttribute(mma_kernel<2>, cudaFuncAttributeMaxDynamicSharedMemorySize, SMEM1);
    cudaFuncSetAttribute(mma_kernel<3>, cudaFuncAttributeMaxDynamicSharedMemorySize, SMEM1);

    // 1) lvl2 prep (2048 blocks) + all setup (3696 blocks) in ONE launch
    prep2_setup_kernel<<<5744, 256>>>(lvl2, op_ids, lc, rc, tc, comp_ids, comp_table,
                                      W1b, b1b, W2b, W1t, b1t, W2t, op_table,
                                      lvl1, lvl0);

    // 2) lvl2 GEMM1 + GEMM2 (GEMM2 writes X1 + child1 directly)
    mma_kernel<0><<<dim3(128, 4), 256, SMEM0>>>(
        p_Xt, p_W1t, p_opb_t, 12, 32,
        p_Xb, p_W1b, p_opb_b, 8,
        p_op2, p_H, nullptr, nullptr, nullptr, nullptr, gamma, beta, nullptr);
    mma_kernel<1><<<256, 256, SMEM1>>>(
        p_H, p_W2t, b2t, 8, 64,
        nullptr, p_W2b, b2b, 8,
        nullptr, nullptr, p_R2, nullptr, p_X1, p_c1, gamma, beta, nullptr);

    // 3) lvl1 GEMM1 + GEMM2 (writes X0 + child0)
    mma_kernel<0><<<dim3(64, 4), 256, SMEM0>>>(
        p_X1, p_W1b, p_opb_b, 8, 64,
        p_X1, p_W1b, p_opb_b, 8,
        p_op1, p_H, nullptr, nullptr, nullptr, nullptr, gamma, beta, nullptr);
    mma_kernel<2><<<128, 256, SMEM1>>>(
        p_H, p_W2b, b2b, 8, 128,
        nullptr, p_W2b, b2b, 8,
        nullptr, nullptr, nullptr, p_c1, p_X0, p_c0, gamma, beta, nullptr);

    // 4) lvl0 GEMM1 + GEMM2 -> dense out
    mma_kernel<0><<<dim3(32, 4), 256, SMEM0>>>(
        p_X0, p_W1b, p_opb_b, 8, 32,
        p_X0, p_W1b, p_opb_b, 8,
        p_op0, p_H, nullptr, nullptr, nullptr, nullptr, gamma, beta, nullptr);
    mma_kernel<3><<<64, 256, SMEM1>>>(
        p_H, p_W2b, b2b, 8, 64,
        nullptr, p_W2b, b2b, 8,
        nullptr, nullptr, nullptr, p_c0, nullptr, nullptr, gamma, beta, out);

    (void)n_in; (void)out_size;
}